// round 3
// baseline (speedup 1.0000x reference)
#include <cuda_runtime.h>
#include <cuda_fp16.h>
#include <cstdint>

// ---------------------------------------------------------------------------
// y[b,l,h,w] = sum_{j,k,i} A[(b,h,w),(j,k,i)] * W[j,k,i,l]
// GEMM: D[512, 6272] = Wmat[512,2304] * Amat[6272,2304]^T  (fp16 in, f32 acc)
// Plain sm_100 target: mma.sync m16n8k16 + ldmatrix + cp.async (no tcgen05).
// ---------------------------------------------------------------------------

#define KTOT   2304
#define KC     32          // K elems per pipeline stage
#define NKC    72          // 2304 / 32
#define MT     4           // M tiles of 128  (M = 512)
#define NT     49          // N tiles of 128  (N = 6272)
#define BLKB   8192        // one 128x32 fp16 tile block in global (dense)
#define SPITCH 80          // smem row pitch bytes (32 fp16 = 64B, padded to 80)
#define STILE  (128 * SPITCH)          // 10240 B
#define STAGE_BYTES (2 * STILE)        // W tile + A tile = 20480
#define STAGES 4
#define GEMM_SMEM (STAGES * STAGE_BYTES)   // 81920

__device__ __align__(128) unsigned char g_W[MT * NKC * BLKB];   // 2.36 MB
__device__ __align__(128) unsigned char g_A[NT * NKC * BLKB];   // 28.9 MB

// ---------------------------------------------------------------------------
// helpers
// ---------------------------------------------------------------------------
__device__ __forceinline__ uint32_t smem_u32(const void* p) {
    uint32_t a;
    asm("{ .reg .u64 t; cvta.to.shared.u64 t, %1; cvt.u32.u64 %0, t; }"
        : "=r"(a) : "l"(p));
    return a;
}
__device__ __forceinline__ void cpa16(uint32_t dst, const void* src) {
    asm volatile("cp.async.cg.shared.global [%0], [%1], 16;"
                 :: "r"(dst), "l"(src) : "memory");
}
__device__ __forceinline__ void cp_commit() {
    asm volatile("cp.async.commit_group;" ::: "memory");
}
__device__ __forceinline__ void cp_wait2() {
    asm volatile("cp.async.wait_group 2;" ::: "memory");
}
__device__ __forceinline__ void ldsm4(uint32_t* r, uint32_t addr) {
    asm volatile("ldmatrix.sync.aligned.m8n8.x4.shared.b16 {%0,%1,%2,%3}, [%4];"
                 : "=r"(r[0]), "=r"(r[1]), "=r"(r[2]), "=r"(r[3]) : "r"(addr));
}
__device__ __forceinline__ void mma16816(float* c, const uint32_t* a, const uint32_t* b) {
    asm volatile("mma.sync.aligned.m16n8k16.row.col.f32.f16.f16.f32 "
                 "{%0,%1,%2,%3}, {%4,%5,%6,%7}, {%8,%9}, {%0,%1,%2,%3};"
                 : "+f"(c[0]), "+f"(c[1]), "+f"(c[2]), "+f"(c[3])
                 : "r"(a[0]), "r"(a[1]), "r"(a[2]), "r"(a[3]),
                   "r"(b[0]), "r"(b[1]));
}
__device__ __forceinline__ uint32_t pack_f16x2(float lo, float hi) {
    uint32_t u;
    asm("cvt.rn.f16x2.f32 %0, %1, %2;" : "=r"(u) : "f"(hi), "f"(lo));
    return u;
}

// ---------------------------------------------------------------------------
// Kernel 1: W[j,k,i,l] f32 -> g_W fp16, [mt][kc][128 rows(l) x 32 cols] dense.
//   kk = (k*3+i)*256 + j  (j fastest).  Threads walk l fastest (coalesced rd).
// ---------------------------------------------------------------------------
__global__ void wtrans_kernel(const float* __restrict__ Wt) {
    int t = blockIdx.x * 256 + threadIdx.x;    // 1152 * 512 total
    if (t >= 1152 * 512) return;
    int kkp = t >> 9, l = t & 511;
    int kk = kkp << 1;                          // even kk; pair (kk, kk+1)
    int ki = kk >> 8, j = kk & 255;
    int k = (ki * 11) >> 5, i = ki - 3 * k;
    float v0 = Wt[(size_t)((j * 3 + k) * 3 + i) * 512 + l];
    float v1 = Wt[(size_t)(((j + 1) * 3 + k) * 3 + i) * 512 + l];
    uint32_t u = pack_f16x2(v0, v1);
    int mt = l >> 7, r = l & 127, ks = kk >> 5, c2 = (kk & 31) * 2;
    *reinterpret_cast<uint32_t*>(g_W + (size_t)(mt * NKC + ks) * BLKB
                                 + r * 64 + c2) = u;
}

// ---------------------------------------------------------------------------
// Kernel 2: x -> g_A fp16, [nt][kc][128 rows(n) x 32 cols] dense.  1 CTA / b.
// A[(b,h,w),(j,k,i)] = [0<=w+i-1<7] * ( [0<=hp+k-1<7]*x[b,256+j,hp+k-1,w2]
//                                     + [0<=h +k-1<7]*x[b,    j,h +k-1,w2] )
//   hp = (h-1)%7,  w2 = (w+i-2)%7
// ---------------------------------------------------------------------------
__global__ __launch_bounds__(256, 1) void atrans_kernel(const float* __restrict__ x) {
    extern __shared__ float xs[];               // 512*49 floats (100 KB)
    int b = blockIdx.x, tid = threadIdx.x;
    const float* xb = x + (size_t)b * 25088;
    for (int idx = tid; idx < 25088; idx += 256) xs[idx] = xb[idx];
    __syncthreads();

    int wid = tid >> 5, lane = tid & 31;
    for (int pos = wid; pos < 49; pos += 8) {
        int h = pos / 7, w = pos - 7 * h;
        int hp = (h == 0) ? 6 : h - 1;
        int n = b * 49 + pos;
        int nt = n >> 7, rr = n & 127;
        unsigned char* base = g_A + (size_t)nt * NKC * BLKB + rr * 64;
        for (int kkp = lane; kkp < 1152; kkp += 32) {
            int kk = kkp << 1;
            int ki = kk >> 8, j = kk & 255;
            int k = (ki * 11) >> 5, i = ki - 3 * k;
            int ww1 = w + i - 1;
            float v0 = 0.f, v1 = 0.f;
            if ((unsigned)ww1 < 7u) {
                int w2 = (ww1 == 0) ? 6 : (ww1 - 1);
                int r1 = hp + k - 1, r2 = h + k - 1;
                const float* xa = xs + w2;
                if ((unsigned)r1 < 7u) {
                    int o = (256 + j) * 49 + r1 * 7;
                    v0 += xa[o]; v1 += xa[o + 49];
                }
                if ((unsigned)r2 < 7u) {
                    int o = j * 49 + r2 * 7;
                    v0 += xa[o]; v1 += xa[o + 49];
                }
            }
            uint32_t u = pack_f16x2(v0, v1);
            int ks = kk >> 5, c2 = (kk & 31) * 2;
            *reinterpret_cast<uint32_t*>(base + (size_t)ks * BLKB + c2) = u;
        }
    }
}

// ---------------------------------------------------------------------------
// Kernel 3: HMMA GEMM.  196 CTAs = 4 mt x 49 nt, CTA tile 128x128, K = 2304.
// 4-stage cp.async pipeline, warp tile 64x32 (2x4 warp grid), smem pitch 80B
// (conflict-free ldmatrix without XOR swizzle: (5r+c) mod 8 is a bijection).
// ---------------------------------------------------------------------------
__device__ __forceinline__ void issue_stage(const unsigned char* wp,
                                            const unsigned char* ap,
                                            uint32_t sbuf, int tid) {
#pragma unroll
    for (int r = 0; r < 2; r++) {
        int id = tid + (r << 8);                       // 0..511
        uint32_t off = (uint32_t)(id >> 2) * SPITCH + (uint32_t)(id & 3) * 16;
        cpa16(sbuf + off, wp + id * 16);
        cpa16(sbuf + STILE + off, ap + id * 16);
    }
}

__global__ __launch_bounds__(256, 1) void gemm_kernel(float* __restrict__ out) {
    extern __shared__ __align__(128) unsigned char smem[];
    uint32_t sb = smem_u32(smem);

    int tid = threadIdx.x, wid = tid >> 5, lane = tid & 31;
    int mt = blockIdx.x / NT, nt = blockIdx.x - mt * NT;
    int wm = wid & 1, wn = wid >> 1;                   // 2 x 4 warp grid

    const unsigned char* wsrc = g_W + (size_t)mt * NKC * BLKB;
    const unsigned char* asrc = g_A + (size_t)nt * NKC * BLKB;

    // per-thread ldmatrix source addresses (stage-relative)
    uint32_t aoff = (uint32_t)(wm * 64 + (lane & 15)) * SPITCH + (lane >> 4) * 16;
    uint32_t boff = STILE
        + (uint32_t)(wn * 32 + (lane & 7) + ((lane & 16) >> 1)) * SPITCH
        + ((lane >> 3) & 1) * 16;

    float acc[4][4][4];
#pragma unroll
    for (int mi = 0; mi < 4; mi++)
#pragma unroll
        for (int ni = 0; ni < 4; ni++)
#pragma unroll
            for (int r = 0; r < 4; r++) acc[mi][ni][r] = 0.f;

    // prologue: fill 3 stages
#pragma unroll
    for (int s = 0; s < STAGES - 1; s++) {
        issue_stage(wsrc + (size_t)s * BLKB, asrc + (size_t)s * BLKB,
                    sb + s * STAGE_BYTES, tid);
        cp_commit();
    }

#pragma unroll 1
    for (int ks = 0; ks < NKC; ks++) {
        cp_wait2();
        __syncthreads();
        int nks = ks + STAGES - 1;
        if (nks < NKC)
            issue_stage(wsrc + (size_t)nks * BLKB, asrc + (size_t)nks * BLKB,
                        sb + (nks & (STAGES - 1)) * STAGE_BYTES, tid);
        cp_commit();

        uint32_t sbuf = sb + (ks & (STAGES - 1)) * STAGE_BYTES;
#pragma unroll
        for (int kst = 0; kst < 2; kst++) {
            uint32_t a[4][4], bfr[2][4];
#pragma unroll
            for (int mi = 0; mi < 4; mi++)
                ldsm4(a[mi], sbuf + aoff + kst * 32 + mi * (16 * SPITCH));
#pragma unroll
            for (int np = 0; np < 2; np++)
                ldsm4(bfr[np], sbuf + boff + kst * 32 + np * (16 * SPITCH));
#pragma unroll
            for (int mi = 0; mi < 4; mi++)
#pragma unroll
                for (int ni = 0; ni < 4; ni++)
                    mma16816(acc[mi][ni], a[mi], &bfr[ni >> 1][(ni & 1) * 2]);
        }
    }

    // epilogue: scatter to out[b][l][h][w];  m = l,  n = b*49 + hw
#pragma unroll
    for (int mi = 0; mi < 4; mi++) {
        int m0 = mt * 128 + wm * 64 + mi * 16 + (lane >> 2);
#pragma unroll
        for (int ni = 0; ni < 4; ni++) {
            int n0 = nt * 128 + wn * 32 + ni * 8 + 2 * (lane & 3);
#pragma unroll
            for (int r = 0; r < 4; r++) {
                int m = m0 + (r >> 1) * 8;
                int n = n0 + (r & 1);
                int bb = n / 49, hw = n - bb * 49;
                out[(size_t)bb * 25088 + (size_t)m * 49 + hw] = acc[mi][ni][r];
            }
        }
    }
}

// ---------------------------------------------------------------------------
extern "C" void kernel_launch(void* const* d_in, const int* in_sizes, int n_in,
                              void* d_out, int out_size) {
    const float* x  = (const float*)d_in[0];   // [128,512,7,7]
    const float* Wt = (const float*)d_in[1];   // [256,3,3,512]
    float* out = (float*)d_out;                // [128,512,7,7]

    cudaFuncSetAttribute(atrans_kernel, cudaFuncAttributeMaxDynamicSharedMemorySize,
                         25088 * (int)sizeof(float));
    cudaFuncSetAttribute(gemm_kernel, cudaFuncAttributeMaxDynamicSharedMemorySize,
                         GEMM_SMEM);

    wtrans_kernel<<<(1152 * 512) / 256, 256>>>(Wt);
    atrans_kernel<<<128, 256, 25088 * sizeof(float)>>>(x);
    gemm_kernel<<<MT * NT, 256, GEMM_SMEM>>>(out);
}

// round 4
// speedup vs baseline: 1.1300x; 1.1300x over previous
#include <cuda_runtime.h>
#include <cuda_fp16.h>
#include <cstdint>

// ---------------------------------------------------------------------------
// y[b,l,h,w] = sum_{j,k,i} A[(b,h,w),(j,k,i)] * W[j,k,i,l]
// GEMM: D[512, 6272] = Wmat[512,2304] * Amat[6272,2304]^T  (fp16 in, f32 acc)
// A is never materialized: A[(b,h,w),(ki, j..j+31)] = gate * g_D[b][s][w2][j..]
// where g_D[b][s][w2][j] precombines the two gather terms (diagonal trick).
// ---------------------------------------------------------------------------

#define KTOT   2304
#define NKC    72          // 2304 / 32 pipeline stages
#define MT     4           // M tiles of 128  (M = 512)
#define NT     49          // N tiles of 128  (N = 6272)
#define BLKB   8192        // one 128x32 fp16 W tile block in global (dense)
#define SPITCH 80          // smem row pitch bytes (32 fp16 = 64B, padded to 80)
#define STILE  (128 * SPITCH)          // 10240 B
#define STAGE_BYTES (2 * STILE)        // W tile + A tile = 20480
#define STAGES 4
#define GEMM_SMEM (STAGES * STAGE_BYTES)   // 81920

#define XSP    516         // dprep smem transpose pitch (floats, 16B-aligned)

__device__ __align__(128) unsigned char g_W[MT * NKC * BLKB];        // 2.36 MB
__device__ __align__(128) __half g_D[128 * 12 * 7 * 256];            // 5.5 MB

// ---------------------------------------------------------------------------
// helpers
// ---------------------------------------------------------------------------
__device__ __forceinline__ uint32_t smem_u32(const void* p) {
    uint32_t a;
    asm("{ .reg .u64 t; cvta.to.shared.u64 t, %1; cvt.u32.u64 %0, t; }"
        : "=r"(a) : "l"(p));
    return a;
}
__device__ __forceinline__ void cpa16(uint32_t dst, const void* src) {
    asm volatile("cp.async.cg.shared.global [%0], [%1], 16;"
                 :: "r"(dst), "l"(src) : "memory");
}
__device__ __forceinline__ void cpa16z(uint32_t dst, const void* src, uint32_t sz) {
    // src-size form: copies sz bytes, zero-fills the rest of the 16.
    asm volatile("cp.async.cg.shared.global [%0], [%1], 16, %2;"
                 :: "r"(dst), "l"(src), "r"(sz) : "memory");
}
__device__ __forceinline__ void cp_commit() {
    asm volatile("cp.async.commit_group;" ::: "memory");
}
__device__ __forceinline__ void cp_wait2() {
    asm volatile("cp.async.wait_group 2;" ::: "memory");
}
__device__ __forceinline__ void ldsm4(uint32_t* r, uint32_t addr) {
    asm volatile("ldmatrix.sync.aligned.m8n8.x4.shared.b16 {%0,%1,%2,%3}, [%4];"
                 : "=r"(r[0]), "=r"(r[1]), "=r"(r[2]), "=r"(r[3]) : "r"(addr));
}
__device__ __forceinline__ void mma16816(float* c, const uint32_t* a, const uint32_t* b) {
    asm volatile("mma.sync.aligned.m16n8k16.row.col.f32.f16.f16.f32 "
                 "{%0,%1,%2,%3}, {%4,%5,%6,%7}, {%8,%9}, {%0,%1,%2,%3};"
                 : "+f"(c[0]), "+f"(c[1]), "+f"(c[2]), "+f"(c[3])
                 : "r"(a[0]), "r"(a[1]), "r"(a[2]), "r"(a[3]),
                   "r"(b[0]), "r"(b[1]));
}
__device__ __forceinline__ uint32_t pack_f16x2(float lo, float hi) {
    uint32_t u;
    asm("cvt.rn.f16x2.f32 %0, %1, %2;" : "=r"(u) : "f"(hi), "f"(lo));
    return u;
}

// ---------------------------------------------------------------------------
// Kernel 1: W[j,k,i,l] f32 -> g_W fp16, [mt][ks][128 rows(l) x 32 cols] dense.
// smem-tiled so BOTH the global reads (contiguous in l) and the global writes
// (contiguous in kk) are coalesced.  Tile: 64 kk x 128 l.
//   kk = (k*3+i)*256 + j  (j fastest)
// ---------------------------------------------------------------------------
__global__ __launch_bounds__(256) void wtrans2_kernel(const float* __restrict__ Wt) {
    __shared__ float ws[64][129];               // [kk_local][l_local(+pad)]
    int tid = threadIdx.x;
    int K0 = blockIdx.x * 64;                   // kk tile base (36 tiles)
    int mt = blockIdx.y;                        // l tile base = mt*128
    int L0 = mt * 128;
    int ks0 = K0 >> 5;

    // load: lanes walk l (coalesced 512B per kk-row)
    int lx = tid & 127;
#pragma unroll
    for (int kl = (tid >> 7); kl < 64; kl += 2) {
        int kk = K0 + kl;
        int j = kk & 255, ki = kk >> 8;
        int k = (ki * 11) >> 5, i = ki - 3 * k;
        ws[kl][lx] = Wt[(size_t)((j * 3 + k) * 3 + i) * 512 + L0 + lx];
    }
    __syncthreads();

    // store: lanes walk kk pairs (coalesced 64B rows)
    int u = tid & 15;                            // pair index within 32-col block
    int rbase = tid >> 4;                        // 0..15
#pragma unroll
    for (int rr = 0; rr < 8; rr++) {
        int rloc = rr * 16 + rbase;              // 0..127
#pragma unroll
        for (int ksb = 0; ksb < 2; ksb++) {
            float v0 = ws[ksb * 32 + 2 * u][rloc];
            float v1 = ws[ksb * 32 + 2 * u + 1][rloc];
            *reinterpret_cast<uint32_t*>(
                g_W + (size_t)(mt * NKC + ks0 + ksb) * BLKB + rloc * 64 + u * 4)
                = pack_f16x2(v0, v1);
        }
    }
}

// ---------------------------------------------------------------------------
// Kernel 2: dprep.  One CTA per batch b.
//  Phase 1: transpose x[b][c][hw] -> xs[hw][c] in smem (pitch XSP).
//  Phase 2: build g_D[b][s][w2][j] (fp16, j contiguous):
//    s in 1..8  (h>=1):  rpA = s-1 (ch j),      rpB = s-2 (ch 256+j)
//    s in 9..11 (h==0):  rpA = s-10 (=k-1),     rpB = s-4 (=k+5)
//    D = gate(rpA) * xs[rpA*7+w2][j] + gate(rpB) * xs[rpB*7+w2][256+j]
// ---------------------------------------------------------------------------
__global__ __launch_bounds__(256, 1) void dprep_kernel(const float* __restrict__ x) {
    extern __shared__ float xs[];               // 49 * XSP floats (~101 KB)
    int b = blockIdx.x, tid = threadIdx.x;
    const float4* xb4 = reinterpret_cast<const float4*>(x + (size_t)b * 25088);

    // Phase 1: vectorized load, scalar scatter into transposed layout
    for (int v = tid; v < 6272; v += 256) {
        float4 f = xb4[v];
        int base = v * 4;
        int c = base / 49, hw = base - c * 49;
        xs[hw * XSP + c] = f.x; if (++hw == 49) { hw = 0; c++; }
        xs[hw * XSP + c] = f.y; if (++hw == 49) { hw = 0; c++; }
        xs[hw * XSP + c] = f.z; if (++hw == 49) { hw = 0; c++; }
        xs[hw * XSP + c] = f.w;
    }
    __syncthreads();

    // Phase 2: 84 (s,w2) combos; warp per combo, lanes cover j in 8-wide chunks
    int wid = tid >> 5, lane = tid & 31;
    for (int combo = wid; combo < 84; combo += 8) {
        int s = combo / 7, w2 = combo - s * 7;
        int rpA, rpB;
        if (s < 9) { rpA = s - 1; rpB = s - 2; }
        else       { rpA = s - 10; rpB = s - 4; }
        bool g1 = (unsigned)rpA < 7u, g2 = (unsigned)rpB < 7u;

        float4 a0 = {0,0,0,0}, a1 = {0,0,0,0}, c0 = {0,0,0,0}, c1 = {0,0,0,0};
        if (g1) {
            const float4* p = reinterpret_cast<const float4*>(
                xs + (rpA * 7 + w2) * XSP + lane * 8);
            a0 = p[0]; a1 = p[1];
        }
        if (g2) {
            const float4* p = reinterpret_cast<const float4*>(
                xs + (rpB * 7 + w2) * XSP + 256 + lane * 8);
            c0 = p[0]; c1 = p[1];
        }
        uint4 o;
        o.x = pack_f16x2(a0.x + c0.x, a0.y + c0.y);
        o.y = pack_f16x2(a0.z + c0.z, a0.w + c0.w);
        o.z = pack_f16x2(a1.x + c1.x, a1.y + c1.y);
        o.w = pack_f16x2(a1.z + c1.z, a1.w + c1.w);
        *reinterpret_cast<uint4*>(
            g_D + ((size_t)(b * 12 + s) * 7 + w2) * 256 + lane * 8) = o;
    }
}

// ---------------------------------------------------------------------------
// Kernel 3: HMMA GEMM.  196 CTAs = 4 mt x 49 nt, CTA tile 128x128, K = 2304.
// 4-stage cp.async pipeline; A tiles gathered directly from g_D (64B rows,
// zero-filled when gated); W tiles bulk-read from g_W.  Warp tile 64x32.
// 80-byte smem pitch = conflict-free ldmatrix without XOR swizzle.
// ---------------------------------------------------------------------------
struct RowCtx { int b, h, w; };

__device__ __forceinline__ void issue_stage(const unsigned char* wp, int ks,
                                            uint32_t sbuf, int tid,
                                            const RowCtx& R0, const RowCtx& R1,
                                            int r0, int q) {
    // W tile: 2 x 16B per thread
#pragma unroll
    for (int r = 0; r < 2; r++) {
        int id = tid + (r << 8);
        uint32_t off = (uint32_t)(id >> 2) * SPITCH + (uint32_t)(id & 3) * 16;
        cpa16(sbuf + off, wp + id * 16);
    }
    // A tile: 2 rows x 16B per thread, gathered from g_D
    int ki = ks >> 3, jc = ks & 7;
    int k = (ki * 11) >> 5, i = ki - 3 * k;
#pragma unroll
    for (int rr = 0; rr < 2; rr++) {
        const RowCtx& R = rr ? R1 : R0;
        int row = r0 + rr * 64;
        int s = (R.h == 0) ? (9 + k) : (R.h + k);
        int ww1 = R.w + i - 1;
        uint32_t sz = ((unsigned)ww1 < 7u) ? 16u : 0u;
        int w2 = (sz == 0) ? 0 : ((ww1 == 0) ? 6 : (ww1 - 1));
        const __half* src = g_D + ((size_t)(R.b * 12 + s) * 7 + w2) * 256
                            + jc * 32 + q * 8;
        uint32_t dst = sbuf + STILE + (uint32_t)row * SPITCH + q * 16;
        cpa16z(dst, src, sz);
    }
}

__global__ __launch_bounds__(256, 1) void gemm_kernel(float* __restrict__ out) {
    extern __shared__ __align__(128) unsigned char smem[];
    uint32_t sb = smem_u32(smem);

    int tid = threadIdx.x, wid = tid >> 5, lane = tid & 31;
    int mt = blockIdx.x / NT, nt = blockIdx.x - mt * NT;
    int wm = wid & 1, wn = wid >> 1;                   // 2 x 4 warp grid

    const unsigned char* wsrc = g_W + (size_t)mt * NKC * BLKB;

    // per-thread A-gather context (rows r0 and r0+64, quarter q)
    int r0 = tid >> 2, q = tid & 3;
    RowCtx R0, R1;
    {
        int n = nt * 128 + r0;
        R0.b = n / 49; int p = n - R0.b * 49; R0.h = p / 7; R0.w = p - R0.h * 7;
        n += 64;
        R1.b = n / 49; p = n - R1.b * 49; R1.h = p / 7; R1.w = p - R1.h * 7;
    }

    // per-thread ldmatrix source addresses (stage-relative)
    uint32_t aoff = (uint32_t)(wm * 64 + (lane & 15)) * SPITCH + (lane >> 4) * 16;
    uint32_t boff = STILE
        + (uint32_t)(wn * 32 + (lane & 7) + ((lane & 16) >> 1)) * SPITCH
        + ((lane >> 3) & 1) * 16;

    float acc[4][4][4];
#pragma unroll
    for (int mi = 0; mi < 4; mi++)
#pragma unroll
        for (int ni = 0; ni < 4; ni++)
#pragma unroll
            for (int r = 0; r < 4; r++) acc[mi][ni][r] = 0.f;

    // prologue: fill 3 stages
#pragma unroll
    for (int s = 0; s < STAGES - 1; s++) {
        issue_stage(wsrc + (size_t)s * BLKB, s, sb + s * STAGE_BYTES,
                    tid, R0, R1, r0, q);
        cp_commit();
    }

#pragma unroll 1
    for (int ks = 0; ks < NKC; ks++) {
        cp_wait2();
        __syncthreads();
        int nks = ks + STAGES - 1;
        if (nks < NKC)
            issue_stage(wsrc + (size_t)nks * BLKB, nks,
                        sb + (nks & (STAGES - 1)) * STAGE_BYTES,
                        tid, R0, R1, r0, q);
        cp_commit();

        uint32_t sbuf = sb + (ks & (STAGES - 1)) * STAGE_BYTES;
#pragma unroll
        for (int kst = 0; kst < 2; kst++) {
            uint32_t a[4][4], bfr[2][4];
#pragma unroll
            for (int mi = 0; mi < 4; mi++)
                ldsm4(a[mi], sbuf + aoff + kst * 32 + mi * (16 * SPITCH));
#pragma unroll
            for (int np = 0; np < 2; np++)
                ldsm4(bfr[np], sbuf + boff + kst * 32 + np * (16 * SPITCH));
#pragma unroll
            for (int mi = 0; mi < 4; mi++)
#pragma unroll
                for (int ni = 0; ni < 4; ni++)
                    mma16816(acc[mi][ni], a[mi], &bfr[ni >> 1][(ni & 1) * 2]);
        }
    }

    // epilogue: scatter to out[b][l][h][w];  m = l,  n = b*49 + hw
#pragma unroll
    for (int mi = 0; mi < 4; mi++) {
        int m0 = mt * 128 + wm * 64 + mi * 16 + (lane >> 2);
#pragma unroll
        for (int ni = 0; ni < 4; ni++) {
            int n0 = nt * 128 + wn * 32 + ni * 8 + 2 * (lane & 3);
#pragma unroll
            for (int r = 0; r < 4; r++) {
                int m = m0 + (r >> 1) * 8;
                int n = n0 + (r & 1);
                int bb = n / 49, hw = n - bb * 49;
                out[(size_t)bb * 25088 + (size_t)m * 49 + hw] = acc[mi][ni][r];
            }
        }
    }
}

// ---------------------------------------------------------------------------
extern "C" void kernel_launch(void* const* d_in, const int* in_sizes, int n_in,
                              void* d_out, int out_size) {
    const float* x  = (const float*)d_in[0];   // [128,512,7,7]
    const float* Wt = (const float*)d_in[1];   // [256,3,3,512]
    float* out = (float*)d_out;                // [128,512,7,7]

    cudaFuncSetAttribute(dprep_kernel, cudaFuncAttributeMaxDynamicSharedMemorySize,
                         49 * XSP * (int)sizeof(float));
    cudaFuncSetAttribute(gemm_kernel, cudaFuncAttributeMaxDynamicSharedMemorySize,
                         GEMM_SMEM);

    wtrans2_kernel<<<dim3(36, 4), 256>>>(Wt);
    dprep_kernel<<<128, 256, 49 * XSP * sizeof(float)>>>(x);
    gemm_kernel<<<MT * NT, 256, GEMM_SMEM>>>(out);
}

// round 5
// speedup vs baseline: 1.4376x; 1.2722x over previous
#include <cuda_runtime.h>
#include <cuda_fp16.h>
#include <cstdint>

// ---------------------------------------------------------------------------
// y[b,l,h,w] = sum_{j,k,i} A[(b,h,w),(j,k,i)] * W[j,k,i,l]
// GEMM: D[512, 6272] = Wmat[512,2304] * Amat[6272,2304]^T  (fp16 in, f32 acc)
// A is never materialized: A[(b,h,w),(ki, j..j+31)] = gate * g_D[b][s][w2][j..]
// where g_D[b][s][w2][j] precombines the two gather terms (diagonal trick).
// ---------------------------------------------------------------------------

#define KTOT   2304
#define NKC    72          // 2304 / 32 pipeline stages
#define MT     4           // M tiles of 128  (M = 512)
#define NT     49          // N tiles of 128  (N = 6272)
#define BLKB   8192        // one 128x32 fp16 W tile block in global (dense)
#define SPITCH 80          // smem row pitch bytes (32 fp16 = 64B, padded to 80)
#define STILE  (128 * SPITCH)          // 10240 B
#define STAGE_BYTES (2 * STILE)        // W tile + A tile = 20480
#define STAGES 4
#define GEMM_SMEM (STAGES * STAGE_BYTES)   // 81920  (x2 CTAs = 160K < 227K)

#define XSP    516         // dprep smem transpose pitch (floats, 16B-aligned)

__device__ __align__(128) unsigned char g_W[MT * NKC * BLKB];        // 2.36 MB
__device__ __align__(128) __half g_D[128 * 12 * 7 * 256];            // 5.5 MB

// ---------------------------------------------------------------------------
// helpers
// ---------------------------------------------------------------------------
__device__ __forceinline__ uint32_t smem_u32(const void* p) {
    uint32_t a;
    asm("{ .reg .u64 t; cvta.to.shared.u64 t, %1; cvt.u32.u64 %0, t; }"
        : "=r"(a) : "l"(p));
    return a;
}
__device__ __forceinline__ void cpa16(uint32_t dst, const void* src) {
    asm volatile("cp.async.cg.shared.global [%0], [%1], 16;"
                 :: "r"(dst), "l"(src) : "memory");
}
__device__ __forceinline__ void cpa16z(uint32_t dst, const void* src, uint32_t sz) {
    // src-size form: copies sz bytes, zero-fills the rest of the 16.
    asm volatile("cp.async.cg.shared.global [%0], [%1], 16, %2;"
                 :: "r"(dst), "l"(src), "r"(sz) : "memory");
}
__device__ __forceinline__ void cp_commit() {
    asm volatile("cp.async.commit_group;" ::: "memory");
}
__device__ __forceinline__ void cp_wait2() {
    asm volatile("cp.async.wait_group 2;" ::: "memory");
}
__device__ __forceinline__ void ldsm4(uint32_t* r, uint32_t addr) {
    asm volatile("ldmatrix.sync.aligned.m8n8.x4.shared.b16 {%0,%1,%2,%3}, [%4];"
                 : "=r"(r[0]), "=r"(r[1]), "=r"(r[2]), "=r"(r[3]) : "r"(addr));
}
__device__ __forceinline__ void mma16816(float* c, const uint32_t* a, const uint32_t* b) {
    asm volatile("mma.sync.aligned.m16n8k16.row.col.f32.f16.f16.f32 "
                 "{%0,%1,%2,%3}, {%4,%5,%6,%7}, {%8,%9}, {%0,%1,%2,%3};"
                 : "+f"(c[0]), "+f"(c[1]), "+f"(c[2]), "+f"(c[3])
                 : "r"(a[0]), "r"(a[1]), "r"(a[2]), "r"(a[3]),
                   "r"(b[0]), "r"(b[1]));
}
__device__ __forceinline__ uint32_t pack_f16x2(float lo, float hi) {
    uint32_t u;
    asm("cvt.rn.f16x2.f32 %0, %1, %2;" : "=r"(u) : "f"(hi), "f"(lo));
    return u;
}

// ---------------------------------------------------------------------------
// Kernel 1: W[j,k,i,l] f32 -> g_W fp16, [mt][ks][128 rows(l) x 32 cols] dense.
// smem-tiled so BOTH the global reads (contiguous in l) and the global writes
// (contiguous in kk) are coalesced.  Tile: 64 kk x 128 l.
//   kk = (k*3+i)*256 + j  (j fastest)
// ---------------------------------------------------------------------------
__global__ __launch_bounds__(256) void wtrans2_kernel(const float* __restrict__ Wt) {
    __shared__ float ws[64][129];               // [kk_local][l_local(+pad)]
    int tid = threadIdx.x;
    int K0 = blockIdx.x * 64;                   // kk tile base (36 tiles)
    int mt = blockIdx.y;                        // l tile base = mt*128
    int L0 = mt * 128;
    int ks0 = K0 >> 5;

    // load: lanes walk l (coalesced 512B per kk-row)
    int lx = tid & 127;
#pragma unroll
    for (int kl = (tid >> 7); kl < 64; kl += 2) {
        int kk = K0 + kl;
        int j = kk & 255, ki = kk >> 8;
        int k = (ki * 11) >> 5, i = ki - 3 * k;
        ws[kl][lx] = Wt[(size_t)((j * 3 + k) * 3 + i) * 512 + L0 + lx];
    }
    __syncthreads();

    // store: lanes walk kk pairs (coalesced 64B rows)
    int u = tid & 15;                            // pair index within 32-col block
    int rbase = tid >> 4;                        // 0..15
#pragma unroll
    for (int rr = 0; rr < 8; rr++) {
        int rloc = rr * 16 + rbase;              // 0..127
#pragma unroll
        for (int ksb = 0; ksb < 2; ksb++) {
            float v0 = ws[ksb * 32 + 2 * u][rloc];
            float v1 = ws[ksb * 32 + 2 * u + 1][rloc];
            *reinterpret_cast<uint32_t*>(
                g_W + (size_t)(mt * NKC + ks0 + ksb) * BLKB + rloc * 64 + u * 4)
                = pack_f16x2(v0, v1);
        }
    }
}

// ---------------------------------------------------------------------------
// Kernel 2: dprep.  One CTA per batch b.
//  Phase 1: transpose x[b][c][hw] -> xs[hw][c] in smem (pitch XSP).
//  Phase 2: build g_D[b][s][w2][j] (fp16, j contiguous):
//    s in 1..8  (h>=1):  rpA = s-1 (ch j),      rpB = s-2 (ch 256+j)
//    s in 9..11 (h==0):  rpA = s-10 (=k-1),     rpB = s-4 (=k+5)
//    D = gate(rpA) * xs[rpA*7+w2][j] + gate(rpB) * xs[rpB*7+w2][256+j]
// ---------------------------------------------------------------------------
__global__ __launch_bounds__(256, 1) void dprep_kernel(const float* __restrict__ x) {
    extern __shared__ float xs[];               // 49 * XSP floats (~101 KB)
    int b = blockIdx.x, tid = threadIdx.x;
    const float4* xb4 = reinterpret_cast<const float4*>(x + (size_t)b * 25088);

    // Phase 1: vectorized load, scalar scatter into transposed layout
    for (int v = tid; v < 6272; v += 256) {
        float4 f = xb4[v];
        int base = v * 4;
        int c = base / 49, hw = base - c * 49;
        xs[hw * XSP + c] = f.x; if (++hw == 49) { hw = 0; c++; }
        xs[hw * XSP + c] = f.y; if (++hw == 49) { hw = 0; c++; }
        xs[hw * XSP + c] = f.z; if (++hw == 49) { hw = 0; c++; }
        xs[hw * XSP + c] = f.w;
    }
    __syncthreads();

    // Phase 2: 84 (s,w2) combos; warp per combo, lanes cover j in 8-wide chunks
    int wid = tid >> 5, lane = tid & 31;
    for (int combo = wid; combo < 84; combo += 8) {
        int s = combo / 7, w2 = combo - s * 7;
        int rpA, rpB;
        if (s < 9) { rpA = s - 1; rpB = s - 2; }
        else       { rpA = s - 10; rpB = s - 4; }
        bool g1 = (unsigned)rpA < 7u, g2 = (unsigned)rpB < 7u;

        float4 a0 = {0,0,0,0}, a1 = {0,0,0,0}, c0 = {0,0,0,0}, c1 = {0,0,0,0};
        if (g1) {
            const float4* p = reinterpret_cast<const float4*>(
                xs + (rpA * 7 + w2) * XSP + lane * 8);
            a0 = p[0]; a1 = p[1];
        }
        if (g2) {
            const float4* p = reinterpret_cast<const float4*>(
                xs + (rpB * 7 + w2) * XSP + 256 + lane * 8);
            c0 = p[0]; c1 = p[1];
        }
        uint4 o;
        o.x = pack_f16x2(a0.x + c0.x, a0.y + c0.y);
        o.y = pack_f16x2(a0.z + c0.z, a0.w + c0.w);
        o.z = pack_f16x2(a1.x + c1.x, a1.y + c1.y);
        o.w = pack_f16x2(a1.z + c1.z, a1.w + c1.w);
        *reinterpret_cast<uint4*>(
            g_D + ((size_t)(b * 12 + s) * 7 + w2) * 256 + lane * 8) = o;
    }
}

// ---------------------------------------------------------------------------
// Kernel 3: HMMA GEMM.  196 CTAs = 4 mt x 49 nt, CTA tile 128x128, K = 2304.
// 4-stage cp.async pipeline; A tiles gathered directly from g_D (64B rows,
// zero-filled when gated); W tiles bulk-read from g_W.  Warp tile 64x32.
// 80-byte smem pitch = conflict-free ldmatrix without XOR swizzle.
// __launch_bounds__(256,2): cap regs at 128 so 2 CTAs co-reside per SM —
// hides sync/ldsm/pipeline stalls and absorbs the 196/148 wave tail.
// ---------------------------------------------------------------------------
struct RowCtx { int b, h, w; };

__device__ __forceinline__ void issue_stage(const unsigned char* wp, int ks,
                                            uint32_t sbuf, int tid,
                                            const RowCtx& R0, const RowCtx& R1,
                                            int r0, int q) {
    // W tile: 2 x 16B per thread
#pragma unroll
    for (int r = 0; r < 2; r++) {
        int id = tid + (r << 8);
        uint32_t off = (uint32_t)(id >> 2) * SPITCH + (uint32_t)(id & 3) * 16;
        cpa16(sbuf + off, wp + id * 16);
    }
    // A tile: 2 rows x 16B per thread, gathered from g_D
    int ki = ks >> 3, jc = ks & 7;
    int k = (ki * 11) >> 5, i = ki - 3 * k;
#pragma unroll
    for (int rr = 0; rr < 2; rr++) {
        const RowCtx& R = rr ? R1 : R0;
        int row = r0 + rr * 64;
        int s = (R.h == 0) ? (9 + k) : (R.h + k);
        int ww1 = R.w + i - 1;
        uint32_t sz = ((unsigned)ww1 < 7u) ? 16u : 0u;
        int w2 = (sz == 0) ? 0 : ((ww1 == 0) ? 6 : (ww1 - 1));
        const __half* src = g_D + ((size_t)(R.b * 12 + s) * 7 + w2) * 256
                            + jc * 32 + q * 8;
        uint32_t dst = sbuf + STILE + (uint32_t)row * SPITCH + q * 16;
        cpa16z(dst, src, sz);
    }
}

__global__ __launch_bounds__(256, 2) void gemm_kernel(float* __restrict__ out) {
    extern __shared__ __align__(128) unsigned char smem[];
    uint32_t sb = smem_u32(smem);

    int tid = threadIdx.x, wid = tid >> 5, lane = tid & 31;
    int mt = blockIdx.x / NT, nt = blockIdx.x - mt * NT;
    int wm = wid & 1, wn = wid >> 1;                   // 2 x 4 warp grid

    const unsigned char* wsrc = g_W + (size_t)mt * NKC * BLKB;

    // per-thread A-gather context (rows r0 and r0+64, quarter q)
    int r0 = tid >> 2, q = tid & 3;
    RowCtx R0, R1;
    {
        int n = nt * 128 + r0;
        R0.b = n / 49; int p = n - R0.b * 49; R0.h = p / 7; R0.w = p - R0.h * 7;
        n += 64;
        R1.b = n / 49; p = n - R1.b * 49; R1.h = p / 7; R1.w = p - R1.h * 7;
    }

    // per-thread ldmatrix source addresses (stage-relative)
    uint32_t aoff = (uint32_t)(wm * 64 + (lane & 15)) * SPITCH + (lane >> 4) * 16;
    uint32_t boff = STILE
        + (uint32_t)(wn * 32 + (lane & 7) + ((lane & 16) >> 1)) * SPITCH
        + ((lane >> 3) & 1) * 16;

    float acc[4][4][4];
#pragma unroll
    for (int mi = 0; mi < 4; mi++)
#pragma unroll
        for (int ni = 0; ni < 4; ni++)
#pragma unroll
            for (int r = 0; r < 4; r++) acc[mi][ni][r] = 0.f;

    // prologue: fill 3 stages
#pragma unroll
    for (int s = 0; s < STAGES - 1; s++) {
        issue_stage(wsrc + (size_t)s * BLKB, s, sb + s * STAGE_BYTES,
                    tid, R0, R1, r0, q);
        cp_commit();
    }

#pragma unroll 1
    for (int ks = 0; ks < NKC; ks++) {
        cp_wait2();
        __syncthreads();
        int nks = ks + STAGES - 1;
        if (nks < NKC)
            issue_stage(wsrc + (size_t)nks * BLKB, nks,
                        sb + (nks & (STAGES - 1)) * STAGE_BYTES,
                        tid, R0, R1, r0, q);
        cp_commit();

        uint32_t sbuf = sb + (ks & (STAGES - 1)) * STAGE_BYTES;
#pragma unroll
        for (int kst = 0; kst < 2; kst++) {
            uint32_t a[4][4], bfr[2][4];
#pragma unroll
            for (int mi = 0; mi < 4; mi++)
                ldsm4(a[mi], sbuf + aoff + kst * 32 + mi * (16 * SPITCH));
#pragma unroll
            for (int np = 0; np < 2; np++)
                ldsm4(bfr[np], sbuf + boff + kst * 32 + np * (16 * SPITCH));
#pragma unroll
            for (int mi = 0; mi < 4; mi++)
#pragma unroll
                for (int ni = 0; ni < 4; ni++)
                    mma16816(acc[mi][ni], a[mi], &bfr[ni >> 1][(ni & 1) * 2]);
        }
    }

    // epilogue: scatter to out[b][l][h][w];  m = l,  n = b*49 + hw
#pragma unroll
    for (int mi = 0; mi < 4; mi++) {
        int m0 = mt * 128 + wm * 64 + mi * 16 + (lane >> 2);
#pragma unroll
        for (int ni = 0; ni < 4; ni++) {
            int n0 = nt * 128 + wn * 32 + ni * 8 + 2 * (lane & 3);
#pragma unroll
            for (int r = 0; r < 4; r++) {
                int m = m0 + (r >> 1) * 8;
                int n = n0 + (r & 1);
                int bb = n / 49, hw = n - bb * 49;
                out[(size_t)bb * 25088 + (size_t)m * 49 + hw] = acc[mi][ni][r];
            }
        }
    }
}

// ---------------------------------------------------------------------------
extern "C" void kernel_launch(void* const* d_in, const int* in_sizes, int n_in,
                              void* d_out, int out_size) {
    const float* x  = (const float*)d_in[0];   // [128,512,7,7]
    const float* Wt = (const float*)d_in[1];   // [256,3,3,512]
    float* out = (float*)d_out;                // [128,512,7,7]

    cudaFuncSetAttribute(dprep_kernel, cudaFuncAttributeMaxDynamicSharedMemorySize,
                         49 * XSP * (int)sizeof(float));
    cudaFuncSetAttribute(gemm_kernel, cudaFuncAttributeMaxDynamicSharedMemorySize,
                         GEMM_SMEM);

    wtrans2_kernel<<<dim3(36, 4), 256>>>(Wt);
    dprep_kernel<<<128, 256, 49 * XSP * sizeof(float)>>>(x);
    gemm_kernel<<<MT * NT, 256, GEMM_SMEM>>>(out);
}

// round 7
// speedup vs baseline: 1.5418x; 1.0725x over previous
#include <cuda_runtime.h>
#include <cuda_fp16.h>
#include <cstdint>

// ---------------------------------------------------------------------------
// y[b,l,h,w] = sum_{j,k,i} A[(b,h,w),(j,k,i)] * W[j,k,i,l]
// GEMM: D[512, 6272] = Wmat[512,2304] * Amat[6272,2304]^T  (fp16 in, f32 acc)
// A is never materialized: A[(b,h,w),(ki, j..j+31)] = gate * g_D[b][s][w2][j..]
// GEMM tile 128x64 (392 CTAs, occ 2) to cut wave-quantization 2.0T -> 1.5T.
// ---------------------------------------------------------------------------

#define KTOT   2304
#define NKC    72          // 2304 / 32 pipeline stages
#define MT     4           // M tiles of 128  (M = 512)
#define NT2    98          // N tiles of 64   (N = 6272)
#define BLKB   8192        // one 128x32 fp16 W tile block in global (dense)
#define SPITCH 80          // smem row pitch bytes (32 fp16 = 64B, padded to 80)
#define STILE_W (128 * SPITCH)         // 10240 B
#define STILE_A (64 * SPITCH)          // 5120 B
#define STAGE_BYTES (STILE_W + STILE_A)  // 15360
#define STAGES 4
#define GEMM_SMEM (STAGES * STAGE_BYTES)   // 61440 (x2 CTAs = 120K < 227K)

#define XSP    516         // dprep smem transpose pitch (floats, 16B-aligned)
#define PREP_SMEM (49 * XSP * 4)       // 101 KB (dprep part dominates)

__device__ __align__(128) unsigned char g_W[MT * NKC * BLKB];        // 2.36 MB
__device__ __align__(128) __half g_D[128 * 12 * 7 * 256];            // 5.5 MB

// ---------------------------------------------------------------------------
// helpers
// ---------------------------------------------------------------------------
__device__ __forceinline__ uint32_t smem_u32(const void* p) {
    uint32_t a;
    asm("{ .reg .u64 t; cvta.to.shared.u64 t, %1; cvt.u32.u64 %0, t; }"
        : "=r"(a) : "l"(p));
    return a;
}
__device__ __forceinline__ void cpa16(uint32_t dst, const void* src) {
    asm volatile("cp.async.cg.shared.global [%0], [%1], 16;"
                 :: "r"(dst), "l"(src) : "memory");
}
__device__ __forceinline__ void cpa16z(uint32_t dst, const void* src, uint32_t sz) {
    asm volatile("cp.async.cg.shared.global [%0], [%1], 16, %2;"
                 :: "r"(dst), "l"(src), "r"(sz) : "memory");
}
__device__ __forceinline__ void cp_commit() {
    asm volatile("cp.async.commit_group;" ::: "memory");
}
__device__ __forceinline__ void cp_wait2() {
    asm volatile("cp.async.wait_group 2;" ::: "memory");
}
__device__ __forceinline__ void ldsm4(uint32_t* r, uint32_t addr) {
    asm volatile("ldmatrix.sync.aligned.m8n8.x4.shared.b16 {%0,%1,%2,%3}, [%4];"
                 : "=r"(r[0]), "=r"(r[1]), "=r"(r[2]), "=r"(r[3]) : "r"(addr));
}
__device__ __forceinline__ void mma16816(float* c, const uint32_t* a, const uint32_t* b) {
    asm volatile("mma.sync.aligned.m16n8k16.row.col.f32.f16.f16.f32 "
                 "{%0,%1,%2,%3}, {%4,%5,%6,%7}, {%8,%9}, {%0,%1,%2,%3};"
                 : "+f"(c[0]), "+f"(c[1]), "+f"(c[2]), "+f"(c[3])
                 : "r"(a[0]), "r"(a[1]), "r"(a[2]), "r"(a[3]),
                   "r"(b[0]), "r"(b[1]));
}
__device__ __forceinline__ uint32_t pack_f16x2(float lo, float hi) {
    uint32_t u;
    asm("cvt.rn.f16x2.f32 %0, %1, %2;" : "=r"(u) : "f"(hi), "f"(lo));
    return u;
}

// ---------------------------------------------------------------------------
// Fused prep kernel.  blocks [0,128) : dprep (b = blockIdx.x)
//                     blocks [128,272) : wtrans (tile id = blockIdx.x - 128)
// ---------------------------------------------------------------------------
__global__ __launch_bounds__(256, 1) void prep_kernel(const float* __restrict__ x,
                                                      const float* __restrict__ Wt) {
    extern __shared__ float dynsm[];
    int tid = threadIdx.x;

    if (blockIdx.x >= 128) {
        // ---- wtrans part: W[j,k,i,l] -> g_W fp16 [mt][ks][128 x 32] dense ----
        int t = blockIdx.x - 128;                   // 0..143
        int mt = t / 36;
        int K0 = (t - mt * 36) * 64;
        int L0 = mt * 128;
        int ks0 = K0 >> 5;
        float* ws = dynsm;                          // [64][129]

        int lx = tid & 127;
#pragma unroll
        for (int kl = (tid >> 7); kl < 64; kl += 2) {
            int kk = K0 + kl;
            int j = kk & 255, ki = kk >> 8;
            int k = (ki * 11) >> 5, i = ki - 3 * k;
            ws[kl * 129 + lx] = Wt[(size_t)((j * 3 + k) * 3 + i) * 512 + L0 + lx];
        }
        __syncthreads();

        int u = tid & 15;
        int rbase = tid >> 4;
#pragma unroll
        for (int rr = 0; rr < 8; rr++) {
            int rloc = rr * 16 + rbase;
#pragma unroll
            for (int ksb = 0; ksb < 2; ksb++) {
                float v0 = ws[(ksb * 32 + 2 * u) * 129 + rloc];
                float v1 = ws[(ksb * 32 + 2 * u + 1) * 129 + rloc];
                *reinterpret_cast<uint32_t*>(
                    g_W + (size_t)(mt * NKC + ks0 + ksb) * BLKB + rloc * 64 + u * 4)
                    = pack_f16x2(v0, v1);
            }
        }
        return;
    }

    // ---- dprep part: build g_D[b][s][w2][j] ----
    float* xs = dynsm;                              // 49 * XSP floats
    int b = blockIdx.x;
    const float4* xb4 = reinterpret_cast<const float4*>(x + (size_t)b * 25088);

    for (int v = tid; v < 6272; v += 256) {
        float4 f = xb4[v];
        int base = v * 4;
        int c = base / 49, hw = base - c * 49;
        xs[hw * XSP + c] = f.x; if (++hw == 49) { hw = 0; c++; }
        xs[hw * XSP + c] = f.y; if (++hw == 49) { hw = 0; c++; }
        xs[hw * XSP + c] = f.z; if (++hw == 49) { hw = 0; c++; }
        xs[hw * XSP + c] = f.w;
    }
    __syncthreads();

    int wid = tid >> 5, lane = tid & 31;
    for (int combo = wid; combo < 84; combo += 8) {
        int s = combo / 7, w2 = combo - s * 7;
        int rpA, rpB;
        if (s < 9) { rpA = s - 1; rpB = s - 2; }
        else       { rpA = s - 10; rpB = s - 4; }
        bool g1 = (unsigned)rpA < 7u, g2 = (unsigned)rpB < 7u;

        float4 a0 = {0,0,0,0}, a1 = {0,0,0,0}, c0 = {0,0,0,0}, c1 = {0,0,0,0};
        if (g1) {
            const float4* p = reinterpret_cast<const float4*>(
                xs + (rpA * 7 + w2) * XSP + lane * 8);
            a0 = p[0]; a1 = p[1];
        }
        if (g2) {
            const float4* p = reinterpret_cast<const float4*>(
                xs + (rpB * 7 + w2) * XSP + 256 + lane * 8);
            c0 = p[0]; c1 = p[1];
        }
        uint4 o;
        o.x = pack_f16x2(a0.x + c0.x, a0.y + c0.y);
        o.y = pack_f16x2(a0.z + c0.z, a0.w + c0.w);
        o.z = pack_f16x2(a1.x + c1.x, a1.y + c1.y);
        o.w = pack_f16x2(a1.z + c1.z, a1.w + c1.w);
        *reinterpret_cast<uint4*>(
            g_D + ((size_t)(b * 12 + s) * 7 + w2) * 256 + lane * 8) = o;
    }
}

// ---------------------------------------------------------------------------
// GEMM.  392 CTAs = 4 mt x 98 nt, CTA tile 128x64, K = 2304, occ 2.
// 4-stage cp.async pipeline; warp grid 4(M) x 2(N), warp tile 32x32.
// A rows gathered from g_D (one 16B cp.async per thread per stage).
// ---------------------------------------------------------------------------
struct RowCtx { int b, h, w; };

__device__ __forceinline__ void issue_stage(const unsigned char* wp, int ks,
                                            uint32_t sbuf, int tid,
                                            const RowCtx& R, int r0, int q) {
    // W tile: 512 x 16B chunks (128 rows x 64 data bytes, pitch 80)
#pragma unroll
    for (int rep = 0; rep < 2; rep++) {
        int id = tid + (rep << 8);                 // 0..511
        uint32_t off = (uint32_t)(id >> 2) * SPITCH + (uint32_t)(id & 3) * 16;
        cpa16(sbuf + off, wp + id * 16);
    }
    // A tile: 1 row-quarter per thread, gathered from g_D
    int ki = ks >> 3, jc = ks & 7;
    int k = (ki * 11) >> 5, i = ki - 3 * k;
    int s = (R.h == 0) ? (9 + k) : (R.h + k);
    int ww1 = R.w + i - 1;
    uint32_t sz = ((unsigned)ww1 < 7u) ? 16u : 0u;
    int w2 = (sz == 0) ? 0 : ((ww1 == 0) ? 6 : (ww1 - 1));
    const __half* src = g_D + ((size_t)(R.b * 12 + s) * 7 + w2) * 256
                        + jc * 32 + q * 8;
    cpa16z(sbuf + STILE_W + (uint32_t)r0 * SPITCH + q * 16, src, sz);
}

__global__ __launch_bounds__(256, 2) void gemm_kernel(float* __restrict__ out) {
    extern __shared__ __align__(128) unsigned char smem[];
    uint32_t sb = smem_u32(smem);

    int tid = threadIdx.x, wid = tid >> 5, lane = tid & 31;
    int mt = blockIdx.x / NT2, nt = blockIdx.x - mt * NT2;
    int wm = wid & 3, wn = wid >> 2;                   // 4(M) x 2(N) warp grid

    const unsigned char* wsrc = g_W + (size_t)mt * NKC * BLKB;

    // per-thread A-gather context (row r0, quarter q)
    int r0 = tid >> 2, q = tid & 3;
    RowCtx R;
    {
        int n = nt * 64 + r0;
        R.b = n / 49; int p = n - R.b * 49; R.h = p / 7; R.w = p - R.h * 7;
    }

    // per-thread ldmatrix source addresses (stage-relative)
    uint32_t aoff = (uint32_t)(wm * 32 + (lane & 15)) * SPITCH + (lane >> 4) * 16;
    uint32_t boff = STILE_W
        + (uint32_t)(wn * 32 + (lane & 7) + ((lane & 16) >> 1)) * SPITCH
        + ((lane >> 3) & 1) * 16;

    float acc[2][4][4];
#pragma unroll
    for (int mi = 0; mi < 2; mi++)
#pragma unroll
        for (int ni = 0; ni < 4; ni++)
#pragma unroll
            for (int r = 0; r < 4; r++) acc[mi][ni][r] = 0.f;

    // prologue: fill 3 stages
#pragma unroll
    for (int s = 0; s < STAGES - 1; s++) {
        issue_stage(wsrc + (size_t)s * BLKB, s, sb + s * STAGE_BYTES,
                    tid, R, r0, q);
        cp_commit();
    }

#pragma unroll 1
    for (int ks = 0; ks < NKC; ks++) {
        cp_wait2();
        __syncthreads();
        int nks = ks + STAGES - 1;
        if (nks < NKC)
            issue_stage(wsrc + (size_t)nks * BLKB, nks,
                        sb + (nks & (STAGES - 1)) * STAGE_BYTES,
                        tid, R, r0, q);
        cp_commit();

        uint32_t sbuf = sb + (ks & (STAGES - 1)) * STAGE_BYTES;
#pragma unroll
        for (int kst = 0; kst < 2; kst++) {
            uint32_t a[2][4], bfr[2][4];
#pragma unroll
            for (int mi = 0; mi < 2; mi++)
                ldsm4(a[mi], sbuf + aoff + kst * 32 + mi * (16 * SPITCH));
#pragma unroll
            for (int np = 0; np < 2; np++)
                ldsm4(bfr[np], sbuf + boff + kst * 32 + np * (16 * SPITCH));
#pragma unroll
            for (int mi = 0; mi < 2; mi++)
#pragma unroll
                for (int ni = 0; ni < 4; ni++)
                    mma16816(acc[mi][ni], a[mi], &bfr[ni >> 1][(ni & 1) * 2]);
        }
    }

    // epilogue: scatter to out[b][l][h][w];  m = l,  n = b*49 + hw
#pragma unroll
    for (int mi = 0; mi < 2; mi++) {
        int m0 = mt * 128 + wm * 32 + mi * 16 + (lane >> 2);
#pragma unroll
        for (int ni = 0; ni < 4; ni++) {
            int n0 = nt * 64 + wn * 32 + ni * 8 + 2 * (lane & 3);
#pragma unroll
            for (int r = 0; r < 4; r++) {
                int m = m0 + (r >> 1) * 8;
                int n = n0 + (r & 1);
                int bb = n / 49, hw = n - bb * 49;
                out[(size_t)bb * 25088 + (size_t)m * 49 + hw] = acc[mi][ni][r];
            }
        }
    }
}

// ---------------------------------------------------------------------------
extern "C" void kernel_launch(void* const* d_in, const int* in_sizes, int n_in,
                              void* d_out, int out_size) {
    const float* x  = (const float*)d_in[0];   // [128,512,7,7]
    const float* Wt = (const float*)d_in[1];   // [256,3,3,512]
    float* out = (float*)d_out;                // [128,512,7,7]

    cudaFuncSetAttribute(prep_kernel, cudaFuncAttributeMaxDynamicSharedMemorySize,
                         PREP_SMEM);
    cudaFuncSetAttribute(gemm_kernel, cudaFuncAttributeMaxDynamicSharedMemorySize,
                         GEMM_SMEM);

    prep_kernel<<<272, 256, PREP_SMEM>>>(x, Wt);
    gemm_kernel<<<MT * NT2, 256, GEMM_SMEM>>>(out);
}

// round 8
// speedup vs baseline: 1.5645x; 1.0147x over previous
#include <cuda_runtime.h>
#include <cuda_fp16.h>
#include <cstdint>

// ---------------------------------------------------------------------------
// y[b,l,h,w] = sum_{j,k,i} A[(b,h,w),(j,k,i)] * W[j,k,i,l]
// GEMM: D[512, 6272] = Wmat[512,2304] * Amat[6272,2304]^T  (fp16 in, f32 acc)
// v8: GEMM operands staged with cp.async.bulk (2 per stage) instead of ~14M
// 16B LDGSTS.  Both operands pre-materialized in global as dense 8KB blocks
// with chunk swizzle  chunk' = chunk ^ ((row>>1)&3)  (conflict-free ldmatrix
// at 64B row pitch).  Tiles 128x128, 196 CTAs, occ 2 -> single wave.
// ---------------------------------------------------------------------------

#define NKC    72          // 2304 / 32 K chunks
#define MT     4           // M tiles of 128  (M = 512)
#define NTT    49          // N tiles of 128  (N = 6272)
#define BLKB   8192        // one 128x32 fp16 tile block (128 rows x 64 B)
#define STAGE_BYTES 16384  // W block + A block
#define STAGES 4
#define GEMM_SMEM (1024 + STAGES * STAGE_BYTES)   // 66560 (x2 = 133K)

#define XSP    516         // dprep smem transpose pitch (floats)
#define PREP_SMEM (49 * XSP * 4)

__device__ __align__(128) unsigned char g_W[MT * NKC * BLKB];        // 2.36 MB
__device__ __align__(128) unsigned char g_A[NTT * NKC * BLKB];       // 28.9 MB
__device__ __align__(128) __half g_D[128 * 12 * 7 * 256];            // 5.5 MB

// ---------------------------------------------------------------------------
// helpers
// ---------------------------------------------------------------------------
__device__ __forceinline__ uint32_t smem_u32(const void* p) {
    uint32_t a;
    asm("{ .reg .u64 t; cvta.to.shared.u64 t, %1; cvt.u32.u64 %0, t; }"
        : "=r"(a) : "l"(p));
    return a;
}
__device__ __forceinline__ void mbar_init(uint32_t a, uint32_t cnt) {
    asm volatile("mbarrier.init.shared.b64 [%0], %1;" :: "r"(a), "r"(cnt) : "memory");
}
__device__ __forceinline__ void mbar_expect_tx(uint32_t a, uint32_t bytes) {
    asm volatile("mbarrier.arrive.expect_tx.shared.b64 _, [%0], %1;"
                 :: "r"(a), "r"(bytes) : "memory");
}
__device__ __forceinline__ void mbar_wait(uint32_t mbar, uint32_t parity) {
    uint32_t done;
    asm volatile("{\n\t.reg .pred p;\n\t"
                 "mbarrier.try_wait.parity.acquire.cta.shared::cta.b64 p, [%1], %2;\n\t"
                 "selp.b32 %0,1,0,p;\n\t}"
                 : "=r"(done) : "r"(mbar), "r"(parity) : "memory");
    while (!done) {
        asm volatile("{\n\t.reg .pred p;\n\t"
                     "mbarrier.try_wait.parity.acquire.cta.shared::cta.b64 p, [%1], %2, 0x989680;\n\t"
                     "selp.b32 %0,1,0,p;\n\t}"
                     : "=r"(done) : "r"(mbar), "r"(parity) : "memory");
    }
}
__device__ __forceinline__ void bulk_g2s(uint32_t dst, const void* src,
                                         uint32_t bytes, uint32_t mbar) {
    asm volatile("cp.async.bulk.shared::cluster.global.mbarrier::complete_tx::bytes "
                 "[%0], [%1], %2, [%3];"
                 :: "r"(dst), "l"(src), "r"(bytes), "r"(mbar) : "memory");
}
__device__ __forceinline__ void ldsm4(uint32_t* r, uint32_t addr) {
    asm volatile("ldmatrix.sync.aligned.m8n8.x4.shared.b16 {%0,%1,%2,%3}, [%4];"
                 : "=r"(r[0]), "=r"(r[1]), "=r"(r[2]), "=r"(r[3]) : "r"(addr));
}
__device__ __forceinline__ void mma16816(float* c, const uint32_t* a, const uint32_t* b) {
    asm volatile("mma.sync.aligned.m16n8k16.row.col.f32.f16.f16.f32 "
                 "{%0,%1,%2,%3}, {%4,%5,%6,%7}, {%8,%9}, {%0,%1,%2,%3};"
                 : "+f"(c[0]), "+f"(c[1]), "+f"(c[2]), "+f"(c[3])
                 : "r"(a[0]), "r"(a[1]), "r"(a[2]), "r"(a[3]),
                   "r"(b[0]), "r"(b[1]));
}
__device__ __forceinline__ uint32_t pack_f16x2(float lo, float hi) {
    uint32_t u;
    asm("cvt.rn.f16x2.f32 %0, %1, %2;" : "=r"(u) : "f"(hi), "f"(lo));
    return u;
}

// ---------------------------------------------------------------------------
// prep: blocks [0,128) build g_D;  blocks [128,272) build g_W (swizzled).
// ---------------------------------------------------------------------------
__global__ __launch_bounds__(256, 1) void prep_kernel(const float* __restrict__ x,
                                                      const float* __restrict__ Wt) {
    extern __shared__ float dynsm[];
    int tid = threadIdx.x;

    if (blockIdx.x >= 128) {
        // ---- wtrans: W[j,k,i,l] -> g_W fp16 [mt][ks][128 x 32] swizzled ----
        int t = blockIdx.x - 128;                   // 0..143
        int mt = t / 36;
        int K0 = (t - mt * 36) * 64;
        int L0 = mt * 128;
        int ks0 = K0 >> 5;
        float* ws = dynsm;                          // [64][129]

        int lx = tid & 127;
#pragma unroll
        for (int kl = (tid >> 7); kl < 64; kl += 2) {
            int kk = K0 + kl;
            int j = kk & 255, ki = kk >> 8;
            int k = (ki * 11) >> 5, i = ki - 3 * k;
            ws[kl * 129 + lx] = Wt[(size_t)((j * 3 + k) * 3 + i) * 512 + L0 + lx];
        }
        __syncthreads();

        int u = tid & 15;                           // u>>2 = chunk, u&3 = word
        int rbase = tid >> 4;
#pragma unroll
        for (int rr = 0; rr < 8; rr++) {
            int rloc = rr * 16 + rbase;
            uint32_t swc = ((uint32_t)(u >> 2) ^ ((rloc >> 1) & 3)) << 4;
#pragma unroll
            for (int ksb = 0; ksb < 2; ksb++) {
                float v0 = ws[(ksb * 32 + 2 * u) * 129 + rloc];
                float v1 = ws[(ksb * 32 + 2 * u + 1) * 129 + rloc];
                *reinterpret_cast<uint32_t*>(
                    g_W + (size_t)(mt * NKC + ks0 + ksb) * BLKB
                    + rloc * 64 + swc + (u & 3) * 4) = pack_f16x2(v0, v1);
            }
        }
        return;
    }

    // ---- dprep: build g_D[b][s][w2][j] ----
    float* xs = dynsm;
    int b = blockIdx.x;
    const float4* xb4 = reinterpret_cast<const float4*>(x + (size_t)b * 25088);

    for (int v = tid; v < 6272; v += 256) {
        float4 f = xb4[v];
        int base = v * 4;
        int c = base / 49, hw = base - c * 49;
        xs[hw * XSP + c] = f.x; if (++hw == 49) { hw = 0; c++; }
        xs[hw * XSP + c] = f.y; if (++hw == 49) { hw = 0; c++; }
        xs[hw * XSP + c] = f.z; if (++hw == 49) { hw = 0; c++; }
        xs[hw * XSP + c] = f.w;
    }
    __syncthreads();

    int wid = tid >> 5, lane = tid & 31;
    for (int combo = wid; combo < 84; combo += 8) {
        int s = combo / 7, w2 = combo - s * 7;
        int rpA, rpB;
        if (s < 9) { rpA = s - 1; rpB = s - 2; }
        else       { rpA = s - 10; rpB = s - 4; }
        bool g1 = (unsigned)rpA < 7u, g2 = (unsigned)rpB < 7u;

        float4 a0 = {0,0,0,0}, a1 = {0,0,0,0}, c0 = {0,0,0,0}, c1 = {0,0,0,0};
        if (g1) {
            const float4* p = reinterpret_cast<const float4*>(
                xs + (rpA * 7 + w2) * XSP + lane * 8);
            a0 = p[0]; a1 = p[1];
        }
        if (g2) {
            const float4* p = reinterpret_cast<const float4*>(
                xs + (rpB * 7 + w2) * XSP + 256 + lane * 8);
            c0 = p[0]; c1 = p[1];
        }
        uint4 o;
        o.x = pack_f16x2(a0.x + c0.x, a0.y + c0.y);
        o.y = pack_f16x2(a0.z + c0.z, a0.w + c0.w);
        o.z = pack_f16x2(a1.x + c1.x, a1.y + c1.y);
        o.w = pack_f16x2(a1.z + c1.z, a1.w + c1.w);
        *reinterpret_cast<uint4*>(
            g_D + ((size_t)(b * 12 + s) * 7 + w2) * 256 + lane * 8) = o;
    }
}

// ---------------------------------------------------------------------------
// amat: materialize g_A [nt][ks][128 rows x 64B swizzled] from g_D.
// grid = 49*72 CTAs x 128 threads; thread = one row.
// ---------------------------------------------------------------------------
__global__ __launch_bounds__(128) void amat_kernel() {
    int nt = blockIdx.x / NKC, ks = blockIdx.x - nt * NKC;
    int r = threadIdx.x;
    int ki = ks >> 3, jc = ks & 7;
    int k = (ki * 11) >> 5, i = ki - 3 * k;

    int n = nt * 128 + r;
    int b = n / 49; int p = n - b * 49;
    int h = p / 7, w = p - h * 7;

    int s = (h == 0) ? (9 + k) : (h + k);
    int ww1 = w + i - 1;
    uint4 v[4] = {{0,0,0,0},{0,0,0,0},{0,0,0,0},{0,0,0,0}};
    if ((unsigned)ww1 < 7u) {
        int w2 = (ww1 == 0) ? 6 : (ww1 - 1);
        const uint4* src = reinterpret_cast<const uint4*>(
            g_D + ((size_t)(b * 12 + s) * 7 + w2) * 256 + jc * 32);
#pragma unroll
        for (int c = 0; c < 4; c++) v[c] = src[c];
    }
    uint4* dst = reinterpret_cast<uint4*>(
        g_A + ((size_t)(nt * NKC + ks) << 13) + r * 64);
    uint32_t sw = (r >> 1) & 3;
#pragma unroll
    for (int c = 0; c < 4; c++) dst[c ^ sw] = v[c];
}

// ---------------------------------------------------------------------------
// GEMM.  196 CTAs = 4 mt x 49 nt, tile 128x128, K = 2304, occ 2 (single wave).
// Stages filled by 2 cp.async.bulk + mbarrier; __syncthreads = empty signal.
// Warp grid 2(M) x 4(N), warp tile 64x32.
// ---------------------------------------------------------------------------
__global__ __launch_bounds__(256, 2) void gemm_kernel(float* __restrict__ out) {
    extern __shared__ __align__(1024) unsigned char smem[];
    uint32_t sb = smem_u32(smem);
    const uint32_t FULLB = sb;                 // 4 x 8B mbarriers
    const uint32_t DATA = sb + 1024;

    int tid = threadIdx.x, wid = tid >> 5, lane = tid & 31;
    int mt = blockIdx.x / NTT, nt = blockIdx.x - mt * NTT;
    int wm = wid & 1, wn = wid >> 1;           // 2(M) x 4(N)

    const unsigned char* wsrc = g_W + (size_t)mt * NKC * BLKB;
    const unsigned char* asrc = g_A + (size_t)nt * NKC * BLKB;

    if (tid == 0) {
#pragma unroll
        for (int s = 0; s < STAGES; s++) mbar_init(FULLB + 8 * s, 1);
    }
    asm volatile("fence.proxy.async.shared::cta;" ::: "memory");
    __syncthreads();

    if (tid == 0) {
#pragma unroll
        for (int ip = 0; ip < STAGES - 1; ip++) {
            uint32_t mb = FULLB + 8 * ip;
            mbar_expect_tx(mb, STAGE_BYTES);
            bulk_g2s(DATA + ip * STAGE_BYTES, wsrc + (size_t)ip * BLKB, BLKB, mb);
            bulk_g2s(DATA + ip * STAGE_BYTES + BLKB, asrc + (size_t)ip * BLKB, BLKB, mb);
        }
    }

    // ldsm per-thread addressing (chunk swizzle: ^ ((row>>1)&3))
    uint32_t arow = wm * 64 + (lane & 15);
    uint32_t axor = (arow >> 1) & 3;
    uint32_t ahi = lane >> 4;
    uint32_t aoffb = arow * 64;
    uint32_t brow = wn * 32 + (lane & 7) + ((lane & 16) >> 1);
    uint32_t bxor = (brow >> 1) & 3;
    uint32_t bhi = (lane >> 3) & 1;
    uint32_t boffb = BLKB + brow * 64;

    float acc[4][4][4];
#pragma unroll
    for (int mi = 0; mi < 4; mi++)
#pragma unroll
        for (int ni = 0; ni < 4; ni++)
#pragma unroll
            for (int r = 0; r < 4; r++) acc[mi][ni][r] = 0.f;

#pragma unroll 1
    for (int ks = 0; ks < NKC; ks++) {
        mbar_wait(FULLB + 8 * (ks & 3), (ks >> 2) & 1);
        uint32_t sbuf = DATA + (ks & 3) * STAGE_BYTES;
#pragma unroll
        for (int kst = 0; kst < 2; kst++) {
            uint32_t a[4][4], bfr[2][4];
            uint32_t ac = ((kst * 2 + ahi) ^ axor) << 4;
            uint32_t bc = ((kst * 2 + bhi) ^ bxor) << 4;
#pragma unroll
            for (int mi = 0; mi < 4; mi++)
                ldsm4(a[mi], sbuf + aoffb + mi * 1024 + ac);
#pragma unroll
            for (int np = 0; np < 2; np++)
                ldsm4(bfr[np], sbuf + boffb + np * 1024 + bc);
#pragma unroll
            for (int mi = 0; mi < 4; mi++)
#pragma unroll
                for (int ni = 0; ni < 4; ni++)
                    mma16816(acc[mi][ni], a[mi], &bfr[ni >> 1][(ni & 1) * 2]);
        }
        __syncthreads();                       // everyone done with stage (ks+3)&3's buffer
        if (tid == 0) {
            int ip = ks + STAGES - 1;
            if (ip < NKC) {
                uint32_t mb = FULLB + 8 * (ip & 3);
                mbar_expect_tx(mb, STAGE_BYTES);
                bulk_g2s(DATA + (ip & 3) * STAGE_BYTES, wsrc + (size_t)ip * BLKB, BLKB, mb);
                bulk_g2s(DATA + (ip & 3) * STAGE_BYTES + BLKB, asrc + (size_t)ip * BLKB, BLKB, mb);
            }
        }
    }

    // epilogue: scatter to out[b][l][h][w];  m = l,  n = b*49 + hw
#pragma unroll
    for (int mi = 0; mi < 4; mi++) {
        int m0 = mt * 128 + wm * 64 + mi * 16 + (lane >> 2);
#pragma unroll
        for (int ni = 0; ni < 4; ni++) {
            int n0 = nt * 128 + wn * 32 + ni * 8 + 2 * (lane & 3);
#pragma unroll
            for (int r = 0; r < 4; r++) {
                int m = m0 + (r >> 1) * 8;
                int n = n0 + (r & 1);
                int bb = n / 49, hw = n - bb * 49;
                out[(size_t)bb * 25088 + (size_t)m * 49 + hw] = acc[mi][ni][r];
            }
        }
    }
}

// ---------------------------------------------------------------------------
extern "C" void kernel_launch(void* const* d_in, const int* in_sizes, int n_in,
                              void* d_out, int out_size) {
    const float* x  = (const float*)d_in[0];   // [128,512,7,7]
    const float* Wt = (const float*)d_in[1];   // [256,3,3,512]
    float* out = (float*)d_out;                // [128,512,7,7]

    cudaFuncSetAttribute(prep_kernel, cudaFuncAttributeMaxDynamicSharedMemorySize,
                         PREP_SMEM);
    cudaFuncSetAttribute(gemm_kernel, cudaFuncAttributeMaxDynamicSharedMemorySize,
                         GEMM_SMEM);

    prep_kernel<<<272, 256, PREP_SMEM>>>(x, Wt);
    amat_kernel<<<NTT * NKC, 128>>>();
    gemm_kernel<<<MT * NTT, 256, GEMM_SMEM>>>(out);
}

// round 9
// speedup vs baseline: 1.7995x; 1.1502x over previous
#include <cuda_runtime.h>
#include <cuda_fp16.h>
#include <cstdint>

// ---------------------------------------------------------------------------
// y[b,l,h,w] = sum_{j,k,i} A[(b,h,w),(j,k,i)] * W[j,k,i,l]
// GEMM: D[512, 6272] = Wmat[512,2304] * Amat[6272,2304]^T  (fp16 in, f32 acc)
// v9: prep builds g_A DIRECTLY (g_D + amat kernel eliminated): each warp
// computes one 512B "D-row" (s,w2) in registers and scatters it to all its
// <=9 (pos,ki) A-row targets.  GEMM: 64-K stages (3 x 32KB, 36 iters) to
// halve sync count and double per-warp ILP runs.
// ---------------------------------------------------------------------------

#define NKC    72          // 2304 / 32 K blocks
#define MT     4           // M tiles of 128  (M = 512)
#define NTT    49          // N tiles of 128  (N = 6272)
#define BLKB   8192        // one 128x32 fp16 tile block (128 rows x 64 B)
#define STAGE_BYTES 32768  // 64-K stage: 2 W blocks + 2 A blocks
#define STAGES 3
#define NST    36          // 64-K stages total
#define GEMM_SMEM (1024 + STAGES * STAGE_BYTES)   // 99328 (x2 = 194K < 227K)

#define XSP    516         // prep smem transpose pitch (floats)
#define PREP_SMEM (49 * XSP * 4)

__device__ __align__(128) unsigned char g_W[MT * NKC * BLKB];        // 2.36 MB
__device__ __align__(128) unsigned char g_A[NTT * NKC * BLKB];       // 28.9 MB

// ---------------------------------------------------------------------------
// helpers
// ---------------------------------------------------------------------------
__device__ __forceinline__ uint32_t smem_u32(const void* p) {
    uint32_t a;
    asm("{ .reg .u64 t; cvta.to.shared.u64 t, %1; cvt.u32.u64 %0, t; }"
        : "=r"(a) : "l"(p));
    return a;
}
__device__ __forceinline__ void mbar_init(uint32_t a, uint32_t cnt) {
    asm volatile("mbarrier.init.shared.b64 [%0], %1;" :: "r"(a), "r"(cnt) : "memory");
}
__device__ __forceinline__ void mbar_expect_tx(uint32_t a, uint32_t bytes) {
    asm volatile("mbarrier.arrive.expect_tx.shared.b64 _, [%0], %1;"
                 :: "r"(a), "r"(bytes) : "memory");
}
__device__ __forceinline__ void mbar_wait(uint32_t mbar, uint32_t parity) {
    uint32_t done;
    asm volatile("{\n\t.reg .pred p;\n\t"
                 "mbarrier.try_wait.parity.acquire.cta.shared::cta.b64 p, [%1], %2;\n\t"
                 "selp.b32 %0,1,0,p;\n\t}"
                 : "=r"(done) : "r"(mbar), "r"(parity) : "memory");
    while (!done) {
        asm volatile("{\n\t.reg .pred p;\n\t"
                     "mbarrier.try_wait.parity.acquire.cta.shared::cta.b64 p, [%1], %2, 0x989680;\n\t"
                     "selp.b32 %0,1,0,p;\n\t}"
                     : "=r"(done) : "r"(mbar), "r"(parity) : "memory");
    }
}
__device__ __forceinline__ void bulk_g2s(uint32_t dst, const void* src,
                                         uint32_t bytes, uint32_t mbar) {
    asm volatile("cp.async.bulk.shared::cluster.global.mbarrier::complete_tx::bytes "
                 "[%0], [%1], %2, [%3];"
                 :: "r"(dst), "l"(src), "r"(bytes), "r"(mbar) : "memory");
}
__device__ __forceinline__ void ldsm4(uint32_t* r, uint32_t addr) {
    asm volatile("ldmatrix.sync.aligned.m8n8.x4.shared.b16 {%0,%1,%2,%3}, [%4];"
                 : "=r"(r[0]), "=r"(r[1]), "=r"(r[2]), "=r"(r[3]) : "r"(addr));
}
__device__ __forceinline__ void mma16816(float* c, const uint32_t* a, const uint32_t* b) {
    asm volatile("mma.sync.aligned.m16n8k16.row.col.f32.f16.f16.f32 "
                 "{%0,%1,%2,%3}, {%4,%5,%6,%7}, {%8,%9}, {%0,%1,%2,%3};"
                 : "+f"(c[0]), "+f"(c[1]), "+f"(c[2]), "+f"(c[3])
                 : "r"(a[0]), "r"(a[1]), "r"(a[2]), "r"(a[3]),
                   "r"(b[0]), "r"(b[1]));
}
__device__ __forceinline__ uint32_t pack_f16x2(float lo, float hi) {
    uint32_t u;
    asm("cvt.rn.f16x2.f32 %0, %1, %2;" : "=r"(u) : "f"(hi), "f"(lo));
    return u;
}

// ---------------------------------------------------------------------------
// prep: blocks [0,128) build g_A rows for batch b directly from x;
//       blocks [128,272) build g_W (chunk-swizzled).
// g_A row (n, ks=ki*8+jc):  64B = f16(D[s][w2][jc*32 .. +32)) with
//   s = (h==0) ? 9+k : h+k,  w2 = (ww1==0)?6:ww1-1,  ww1 = w+i-1 (gate 0..6)
//   D[s][w2][j] = gate(rpA)*x[b,j,rpA,w2] + gate(rpB)*x[b,256+j,rpB,w2]
//   chunk swizzle: 16B chunk c stored at c ^ ((row>>1)&3)
// ---------------------------------------------------------------------------
__global__ __launch_bounds__(256, 1) void prep_kernel(const float* __restrict__ x,
                                                      const float* __restrict__ Wt) {
    extern __shared__ float dynsm[];
    int tid = threadIdx.x;

    if (blockIdx.x >= 128) {
        // ---- wtrans: W[j,k,i,l] -> g_W fp16 [mt][ks][128 x 32] swizzled ----
        int t = blockIdx.x - 128;                   // 0..143
        int mt = t / 36;
        int K0 = (t - mt * 36) * 64;
        int L0 = mt * 128;
        int ks0 = K0 >> 5;
        float* ws = dynsm;                          // [64][129]

        int lx = tid & 127;
#pragma unroll
        for (int kl = (tid >> 7); kl < 64; kl += 2) {
            int kk = K0 + kl;
            int j = kk & 255, ki = kk >> 8;
            int k = (ki * 11) >> 5, i = ki - 3 * k;
            ws[kl * 129 + lx] = Wt[(size_t)((j * 3 + k) * 3 + i) * 512 + L0 + lx];
        }
        __syncthreads();

        int u = tid & 15;                           // u>>2 = chunk, u&3 = word
        int rbase = tid >> 4;
#pragma unroll
        for (int rr = 0; rr < 8; rr++) {
            int rloc = rr * 16 + rbase;
            uint32_t swc = ((uint32_t)(u >> 2) ^ ((rloc >> 1) & 3)) << 4;
#pragma unroll
            for (int ksb = 0; ksb < 2; ksb++) {
                float v0 = ws[(ksb * 32 + 2 * u) * 129 + rloc];
                float v1 = ws[(ksb * 32 + 2 * u + 1) * 129 + rloc];
                *reinterpret_cast<uint32_t*>(
                    g_W + (size_t)(mt * NKC + ks0 + ksb) * BLKB
                    + rloc * 64 + swc + (u & 3) * 4) = pack_f16x2(v0, v1);
            }
        }
        return;
    }

    // ---- A build for batch b ----
    float* xs = dynsm;                              // xs[hw][c], pitch XSP
    int b = blockIdx.x;
    const float4* xb4 = reinterpret_cast<const float4*>(x + (size_t)b * 25088);

    for (int v = tid; v < 6272; v += 256) {
        float4 f = xb4[v];
        int base = v * 4;
        int c = base / 49, hw = base - c * 49;
        xs[hw * XSP + c] = f.x; if (++hw == 49) { hw = 0; c++; }
        xs[hw * XSP + c] = f.y; if (++hw == 49) { hw = 0; c++; }
        xs[hw * XSP + c] = f.z; if (++hw == 49) { hw = 0; c++; }
        xs[hw * XSP + c] = f.w;
    }
    __syncthreads();

    int wid = tid >> 5, lane = tid & 31;

    // Phase 2: 77 (s,w2) combos, s in 1..11.  Warp computes the 512B D-row
    // in registers (lane: j = 8*lane .. 8*lane+7) and scatters to targets.
    for (int combo = wid; combo < 77; combo += 8) {
        int s = combo / 7 + 1, w2 = combo - (s - 1) * 7;
        int rpA, rpB;
        if (s < 9) { rpA = s - 1; rpB = s - 2; }
        else       { rpA = s - 10; rpB = s - 4; }
        bool g1 = (unsigned)rpA < 7u, g2 = (unsigned)rpB < 7u;

        float4 a0 = {0,0,0,0}, a1 = {0,0,0,0}, c0 = {0,0,0,0}, c1 = {0,0,0,0};
        if (g1) {
            const float4* p = reinterpret_cast<const float4*>(
                xs + (rpA * 7 + w2) * XSP + lane * 8);
            a0 = p[0]; a1 = p[1];
        }
        if (g2) {
            const float4* p = reinterpret_cast<const float4*>(
                xs + (rpB * 7 + w2) * XSP + 256 + lane * 8);
            c0 = p[0]; c1 = p[1];
        }
        uint4 o;
        o.x = pack_f16x2(a0.x + c0.x, a0.y + c0.y);
        o.y = pack_f16x2(a0.z + c0.z, a0.w + c0.w);
        o.z = pack_f16x2(a1.x + c1.x, a1.y + c1.y);
        o.w = pack_f16x2(a1.z + c1.z, a1.w + c1.w);

        int ww1 = (w2 + 1) % 7;
        int jc = lane >> 2, cw = lane & 3;
        int hlo, hhi;
        if (s >= 9) { hlo = 0; hhi = 0; }
        else { hlo = (s - 2 > 1) ? s - 2 : 1; hhi = (s < 6) ? s : 6; }
#pragma unroll 1
        for (int h = hlo; h <= hhi; h++) {
            int k = (s >= 9) ? (s - 9) : (s - h);
#pragma unroll
            for (int i = 0; i < 3; i++) {
                int w = ww1 + 1 - i;
                if ((unsigned)w < 7u) {
                    int ki = k * 3 + i;
                    int n = b * 49 + h * 7 + w;
                    int nt = n >> 7, row = n & 127;
                    int chunk = cw ^ ((row >> 1) & 3);
                    *reinterpret_cast<uint4*>(
                        g_A + ((size_t)(nt * NKC + ki * 8 + jc) << 13)
                        + row * 64 + chunk * 16) = o;
                }
            }
        }
    }

    // Phase 3: zero the 336 gated rows: (w=0,i=0) and (w=6,i=2), all h,k,jc.
    const uint4 z4 = {0, 0, 0, 0};
    for (int t = tid; t < 1344; t += 256) {
        int c = t & 3;
        int rown = t >> 2;                  // 0..335
        int jc = rown & 7;
        int zz = rown >> 3;                 // 0..41
        int zi = zz / 21;                   // 0:(w=0,i=0)  1:(w=6,i=2)
        int rem = zz - zi * 21;
        int k = rem / 7, h = rem - k * 7;
        int ki = k * 3 + (zi ? 2 : 0);
        int w = zi ? 6 : 0;
        int n = b * 49 + h * 7 + w;
        int nt = n >> 7, row = n & 127;
        *reinterpret_cast<uint4*>(
            g_A + ((size_t)(nt * NKC + ki * 8 + jc) << 13)
            + row * 64 + c * 16) = z4;
    }
}

// ---------------------------------------------------------------------------
// GEMM.  196 CTAs = 4 mt x 49 nt, tile 128x128, K = 2304, occ 2 (single wave).
// 36 stages of K=64 (32KB: 2 W blocks + 2 A blocks), 3-deep, 2 bulk copies
// per stage.  Warp grid 2(M) x 4(N), warp tile 64x32.
// ---------------------------------------------------------------------------
__global__ __launch_bounds__(256, 2) void gemm_kernel(float* __restrict__ out) {
    extern __shared__ __align__(1024) unsigned char smem[];
    uint32_t sb = smem_u32(smem);
    const uint32_t FULLB = sb;                 // 3 x 8B mbarriers
    const uint32_t DATA = sb + 1024;

    int tid = threadIdx.x, wid = tid >> 5, lane = tid & 31;
    int mt = blockIdx.x / NTT, nt = blockIdx.x - mt * NTT;
    int wm = wid & 1, wn = wid >> 1;           // 2(M) x 4(N)

    const unsigned char* wsrc = g_W + (size_t)mt * NKC * BLKB;
    const unsigned char* asrc = g_A + (size_t)nt * NKC * BLKB;

    if (tid == 0) {
#pragma unroll
        for (int s = 0; s < STAGES; s++) mbar_init(FULLB + 8 * s, 1);
    }
    asm volatile("fence.proxy.async.shared::cta;" ::: "memory");
    __syncthreads();

    if (tid == 0) {
#pragma unroll
        for (int ip = 0; ip < STAGES - 1; ip++) {
            uint32_t mb = FULLB + 8 * ip;
            mbar_expect_tx(mb, STAGE_BYTES);
            bulk_g2s(DATA + ip * STAGE_BYTES, wsrc + (size_t)ip * 16384, 16384, mb);
            bulk_g2s(DATA + ip * STAGE_BYTES + 16384, asrc + (size_t)ip * 16384, 16384, mb);
        }
    }

    // ldsm per-thread addressing (chunk swizzle: ^ ((row>>1)&3))
    uint32_t arow = wm * 64 + (lane & 15);
    uint32_t axor = (arow >> 1) & 3;
    uint32_t ahi = lane >> 4;
    uint32_t aoffb = arow * 64;
    uint32_t brow = wn * 32 + (lane & 7) + ((lane & 16) >> 1);
    uint32_t bxor = (brow >> 1) & 3;
    uint32_t bhi = (lane >> 3) & 1;
    uint32_t boffb = brow * 64;

    float acc[4][4][4];
#pragma unroll
    for (int mi = 0; mi < 4; mi++)
#pragma unroll
        for (int ni = 0; ni < 4; ni++)
#pragma unroll
            for (int r = 0; r < 4; r++) acc[mi][ni][r] = 0.f;

#pragma unroll 1
    for (int st = 0; st < NST; st++) {
        int buf = st % 3;
        mbar_wait(FULLB + 8 * buf, (uint32_t)((st / 3) & 1));
        uint32_t sbuf = DATA + buf * STAGE_BYTES;
#pragma unroll
        for (int kst = 0; kst < 4; kst++) {
            uint32_t wbo = (uint32_t)(kst >> 1) * 8192;
            uint32_t ac = (((kst & 1) * 2 + ahi) ^ axor) << 4;
            uint32_t bc = (((kst & 1) * 2 + bhi) ^ bxor) << 4;
            uint32_t a[4][4], bfr[2][4];
#pragma unroll
            for (int mi = 0; mi < 4; mi++)
                ldsm4(a[mi], sbuf + wbo + aoffb + mi * 1024 + ac);
#pragma unroll
            for (int np = 0; np < 2; np++)
                ldsm4(bfr[np], sbuf + 16384 + wbo + boffb + np * 1024 + bc);
#pragma unroll
            for (int mi = 0; mi < 4; mi++)
#pragma unroll
                for (int ni = 0; ni < 4; ni++)
                    mma16816(acc[mi][ni], a[mi], &bfr[ni >> 1][(ni & 1) * 2]);
        }
        __syncthreads();
        if (tid == 0) {
            int ip = st + STAGES - 1;
            if (ip < NST) {
                int pb = ip % 3;
                uint32_t mb = FULLB + 8 * pb;
                mbar_expect_tx(mb, STAGE_BYTES);
                bulk_g2s(DATA + pb * STAGE_BYTES, wsrc + (size_t)ip * 16384, 16384, mb);
                bulk_g2s(DATA + pb * STAGE_BYTES + 16384, asrc + (size_t)ip * 16384, 16384, mb);
            }
        }
    }

    // epilogue: scatter to out[b][l][h][w];  m = l,  n = b*49 + hw
#pragma unroll
    for (int mi = 0; mi < 4; mi++) {
        int m0 = mt * 128 + wm * 64 + mi * 16 + (lane >> 2);
#pragma unroll
        for (int ni = 0; ni < 4; ni++) {
            int n0 = nt * 128 + wn * 32 + ni * 8 + 2 * (lane & 3);
#pragma unroll
            for (int r = 0; r < 4; r++) {
                int m = m0 + (r >> 1) * 8;
                int n = n0 + (r & 1);
                int bb = n / 49, hw = n - bb * 49;
                out[(size_t)bb * 25088 + (size_t)m * 49 + hw] = acc[mi][ni][r];
            }
        }
    }
}

// ---------------------------------------------------------------------------
extern "C" void kernel_launch(void* const* d_in, const int* in_sizes, int n_in,
                              void* d_out, int out_size) {
    const float* x  = (const float*)d_in[0];   // [128,512,7,7]
    const float* Wt = (const float*)d_in[1];   // [256,3,3,512]
    float* out = (float*)d_out;                // [128,512,7,7]

    cudaFuncSetAttribute(prep_kernel, cudaFuncAttributeMaxDynamicSharedMemorySize,
                         PREP_SMEM);
    cudaFuncSetAttribute(gemm_kernel, cudaFuncAttributeMaxDynamicSharedMemorySize,
                         GEMM_SMEM);

    prep_kernel<<<272, 256, PREP_SMEM>>>(x, Wt);
    gemm_kernel<<<MT * NTT, 256, GEMM_SMEM>>>(out);
}

// round 10
// speedup vs baseline: 1.8888x; 1.0497x over previous
#include <cuda_runtime.h>
#include <cuda_fp16.h>
#include <cstdint>

// ---------------------------------------------------------------------------
// y[b,l,h,w] = sum_{j,k,i} A[(b,h,w),(j,k,i)] * W[j,k,i,l]
// GEMM: D[512, 6272] = Wmat[512,2304] * Amat[6272,2304]^T  (fp16 in, f32 acc)
// v10: split-K=3.  588 CTAs of 128x128xK768 write f32 partials (dense,
// L2-resident); reduce kernel sums 3 partials and scatters to NCHW.
// Wave balance: max per-SM work 2.0T -> 1.33T.
// ---------------------------------------------------------------------------

#define NKC    72          // 2304 / 32 K blocks
#define MT     4           // M tiles of 128  (M = 512)
#define NTT    49          // N tiles of 128  (N = 6272)
#define NTILES 196         // MT * NTT
#define BLKB   8192        // one 128x32 fp16 tile block (128 rows x 64 B)
#define STAGE_BYTES 32768  // 64-K stage: 2 W blocks + 2 A blocks
#define STAGES 3
#define KSPLIT 3
#define NSTS   12          // 64-K stages per split (36 / 3)
#define GEMM_SMEM (1024 + STAGES * STAGE_BYTES)   // 99328 (x2 = 194K < 227K)

#define XSP    516         // prep smem transpose pitch (floats)
#define PREP_SMEM (49 * XSP * 4)

__device__ __align__(128) unsigned char g_W[MT * NKC * BLKB];        // 2.36 MB
__device__ __align__(128) unsigned char g_A[NTT * NKC * BLKB];       // 28.9 MB
__device__ __align__(128) float g_P[KSPLIT * NTILES * 16384];        // 38.5 MB

// ---------------------------------------------------------------------------
// helpers
// ---------------------------------------------------------------------------
__device__ __forceinline__ uint32_t smem_u32(const void* p) {
    uint32_t a;
    asm("{ .reg .u64 t; cvta.to.shared.u64 t, %1; cvt.u32.u64 %0, t; }"
        : "=r"(a) : "l"(p));
    return a;
}
__device__ __forceinline__ void mbar_init(uint32_t a, uint32_t cnt) {
    asm volatile("mbarrier.init.shared.b64 [%0], %1;" :: "r"(a), "r"(cnt) : "memory");
}
__device__ __forceinline__ void mbar_expect_tx(uint32_t a, uint32_t bytes) {
    asm volatile("mbarrier.arrive.expect_tx.shared.b64 _, [%0], %1;"
                 :: "r"(a), "r"(bytes) : "memory");
}
__device__ __forceinline__ void mbar_wait(uint32_t mbar, uint32_t parity) {
    uint32_t done;
    asm volatile("{\n\t.reg .pred p;\n\t"
                 "mbarrier.try_wait.parity.acquire.cta.shared::cta.b64 p, [%1], %2;\n\t"
                 "selp.b32 %0,1,0,p;\n\t}"
                 : "=r"(done) : "r"(mbar), "r"(parity) : "memory");
    while (!done) {
        asm volatile("{\n\t.reg .pred p;\n\t"
                     "mbarrier.try_wait.parity.acquire.cta.shared::cta.b64 p, [%1], %2, 0x989680;\n\t"
                     "selp.b32 %0,1,0,p;\n\t}"
                     : "=r"(done) : "r"(mbar), "r"(parity) : "memory");
    }
}
__device__ __forceinline__ void bulk_g2s(uint32_t dst, const void* src,
                                         uint32_t bytes, uint32_t mbar) {
    asm volatile("cp.async.bulk.shared::cluster.global.mbarrier::complete_tx::bytes "
                 "[%0], [%1], %2, [%3];"
                 :: "r"(dst), "l"(src), "r"(bytes), "r"(mbar) : "memory");
}
__device__ __forceinline__ void ldsm4(uint32_t* r, uint32_t addr) {
    asm volatile("ldmatrix.sync.aligned.m8n8.x4.shared.b16 {%0,%1,%2,%3}, [%4];"
                 : "=r"(r[0]), "=r"(r[1]), "=r"(r[2]), "=r"(r[3]) : "r"(addr));
}
__device__ __forceinline__ void mma16816(float* c, const uint32_t* a, const uint32_t* b) {
    asm volatile("mma.sync.aligned.m16n8k16.row.col.f32.f16.f16.f32 "
                 "{%0,%1,%2,%3}, {%4,%5,%6,%7}, {%8,%9}, {%0,%1,%2,%3};"
                 : "+f"(c[0]), "+f"(c[1]), "+f"(c[2]), "+f"(c[3])
                 : "r"(a[0]), "r"(a[1]), "r"(a[2]), "r"(a[3]),
                   "r"(b[0]), "r"(b[1]));
}
__device__ __forceinline__ uint32_t pack_f16x2(float lo, float hi) {
    uint32_t u;
    asm("cvt.rn.f16x2.f32 %0, %1, %2;" : "=r"(u) : "f"(hi), "f"(lo));
    return u;
}

// ---------------------------------------------------------------------------
// prep: blocks [0,128) build g_A rows for batch b directly from x;
//       blocks [128,272) build g_W (chunk-swizzled).
// ---------------------------------------------------------------------------
__global__ __launch_bounds__(256, 1) void prep_kernel(const float* __restrict__ x,
                                                      const float* __restrict__ Wt) {
    extern __shared__ float dynsm[];
    int tid = threadIdx.x;

    if (blockIdx.x >= 128) {
        // ---- wtrans: W[j,k,i,l] -> g_W fp16 [mt][ks][128 x 32] swizzled ----
        int t = blockIdx.x - 128;                   // 0..143
        int mt = t / 36;
        int K0 = (t - mt * 36) * 64;
        int L0 = mt * 128;
        int ks0 = K0 >> 5;
        float* ws = dynsm;                          // [64][129]

        int lx = tid & 127;
#pragma unroll
        for (int kl = (tid >> 7); kl < 64; kl += 2) {
            int kk = K0 + kl;
            int j = kk & 255, ki = kk >> 8;
            int k = (ki * 11) >> 5, i = ki - 3 * k;
            ws[kl * 129 + lx] = Wt[(size_t)((j * 3 + k) * 3 + i) * 512 + L0 + lx];
        }
        __syncthreads();

        int u = tid & 15;                           // u>>2 = chunk, u&3 = word
        int rbase = tid >> 4;
#pragma unroll
        for (int rr = 0; rr < 8; rr++) {
            int rloc = rr * 16 + rbase;
            uint32_t swc = ((uint32_t)(u >> 2) ^ ((rloc >> 1) & 3)) << 4;
#pragma unroll
            for (int ksb = 0; ksb < 2; ksb++) {
                float v0 = ws[(ksb * 32 + 2 * u) * 129 + rloc];
                float v1 = ws[(ksb * 32 + 2 * u + 1) * 129 + rloc];
                *reinterpret_cast<uint32_t*>(
                    g_W + (size_t)(mt * NKC + ks0 + ksb) * BLKB
                    + rloc * 64 + swc + (u & 3) * 4) = pack_f16x2(v0, v1);
            }
        }
        return;
    }

    // ---- A build for batch b ----
    float* xs = dynsm;                              // xs[hw][c], pitch XSP
    int b = blockIdx.x;
    const float4* xb4 = reinterpret_cast<const float4*>(x + (size_t)b * 25088);

    for (int v = tid; v < 6272; v += 256) {
        float4 f = xb4[v];
        int base = v * 4;
        int c = base / 49, hw = base - c * 49;
        xs[hw * XSP + c] = f.x; if (++hw == 49) { hw = 0; c++; }
        xs[hw * XSP + c] = f.y; if (++hw == 49) { hw = 0; c++; }
        xs[hw * XSP + c] = f.z; if (++hw == 49) { hw = 0; c++; }
        xs[hw * XSP + c] = f.w;
    }
    __syncthreads();

    int wid = tid >> 5, lane = tid & 31;

    // Phase 2: 77 (s,w2) combos, s in 1..11.  Warp computes the 512B D-row
    // in registers (lane: j = 8*lane .. 8*lane+7) and scatters to targets.
    for (int combo = wid; combo < 77; combo += 8) {
        int s = combo / 7 + 1, w2 = combo - (s - 1) * 7;
        int rpA, rpB;
        if (s < 9) { rpA = s - 1; rpB = s - 2; }
        else       { rpA = s - 10; rpB = s - 4; }
        bool g1 = (unsigned)rpA < 7u, g2 = (unsigned)rpB < 7u;

        float4 a0 = {0,0,0,0}, a1 = {0,0,0,0}, c0 = {0,0,0,0}, c1 = {0,0,0,0};
        if (g1) {
            const float4* p = reinterpret_cast<const float4*>(
                xs + (rpA * 7 + w2) * XSP + lane * 8);
            a0 = p[0]; a1 = p[1];
        }
        if (g2) {
            const float4* p = reinterpret_cast<const float4*>(
                xs + (rpB * 7 + w2) * XSP + 256 + lane * 8);
            c0 = p[0]; c1 = p[1];
        }
        uint4 o;
        o.x = pack_f16x2(a0.x + c0.x, a0.y + c0.y);
        o.y = pack_f16x2(a0.z + c0.z, a0.w + c0.w);
        o.z = pack_f16x2(a1.x + c1.x, a1.y + c1.y);
        o.w = pack_f16x2(a1.z + c1.z, a1.w + c1.w);

        int ww1 = (w2 + 1) % 7;
        int jc = lane >> 2, cw = lane & 3;
        int hlo, hhi;
        if (s >= 9) { hlo = 0; hhi = 0; }
        else { hlo = (s - 2 > 1) ? s - 2 : 1; hhi = (s < 6) ? s : 6; }
#pragma unroll 1
        for (int h = hlo; h <= hhi; h++) {
            int k = (s >= 9) ? (s - 9) : (s - h);
#pragma unroll
            for (int i = 0; i < 3; i++) {
                int w = ww1 + 1 - i;
                if ((unsigned)w < 7u) {
                    int ki = k * 3 + i;
                    int n = b * 49 + h * 7 + w;
                    int nt = n >> 7, row = n & 127;
                    int chunk = cw ^ ((row >> 1) & 3);
                    *reinterpret_cast<uint4*>(
                        g_A + ((size_t)(nt * NKC + ki * 8 + jc) << 13)
                        + row * 64 + chunk * 16) = o;
                }
            }
        }
    }

    // Phase 3: zero the gated rows: (w=0,i=0) and (w=6,i=2), all h,k,jc.
    const uint4 z4 = {0, 0, 0, 0};
    for (int t = tid; t < 1344; t += 256) {
        int c = t & 3;
        int rown = t >> 2;                  // 0..335
        int jc = rown & 7;
        int zz = rown >> 3;                 // 0..41
        int zi = zz / 21;                   // 0:(w=0,i=0)  1:(w=6,i=2)
        int rem = zz - zi * 21;
        int k = rem / 7, h = rem - k * 7;
        int ki = k * 3 + (zi ? 2 : 0);
        int w = zi ? 6 : 0;
        int n = b * 49 + h * 7 + w;
        int nt = n >> 7, row = n & 127;
        *reinterpret_cast<uint4*>(
            g_A + ((size_t)(nt * NKC + ki * 8 + jc) << 13)
            + row * 64 + c * 16) = z4;
    }
}

// ---------------------------------------------------------------------------
// GEMM.  588 CTAs = 3 splits x (4 mt x 49 nt), tile 128x128 x K768.
// 12 stages of K=64 (32KB), 3-deep, 2 bulk copies per stage, occ 2.
// Dense f32 partial output to g_P.  Warp grid 2(M) x 4(N).
// ---------------------------------------------------------------------------
__global__ __launch_bounds__(256, 2) void gemm_kernel() {
    extern __shared__ __align__(1024) unsigned char smem[];
    uint32_t sb = smem_u32(smem);
    const uint32_t FULLB = sb;                 // 3 x 8B mbarriers
    const uint32_t DATA = sb + 1024;

    int tid = threadIdx.x, wid = tid >> 5, lane = tid & 31;
    int sp = blockIdx.x / NTILES;
    int tile = blockIdx.x - sp * NTILES;
    int mt = tile / NTT, nt = tile - mt * NTT;
    int wm = wid & 1, wn = wid >> 1;           // 2(M) x 4(N)

    const unsigned char* wsrc = g_W + (size_t)mt * NKC * BLKB
                                + (size_t)sp * NSTS * 16384;
    const unsigned char* asrc = g_A + (size_t)nt * NKC * BLKB
                                + (size_t)sp * NSTS * 16384;

    if (tid == 0) {
#pragma unroll
        for (int s = 0; s < STAGES; s++) mbar_init(FULLB + 8 * s, 1);
    }
    asm volatile("fence.proxy.async.shared::cta;" ::: "memory");
    __syncthreads();

    if (tid == 0) {
#pragma unroll
        for (int ip = 0; ip < STAGES - 1; ip++) {
            uint32_t mb = FULLB + 8 * ip;
            mbar_expect_tx(mb, STAGE_BYTES);
            bulk_g2s(DATA + ip * STAGE_BYTES, wsrc + (size_t)ip * 16384, 16384, mb);
            bulk_g2s(DATA + ip * STAGE_BYTES + 16384, asrc + (size_t)ip * 16384, 16384, mb);
        }
    }

    // ldsm per-thread addressing (chunk swizzle: ^ ((row>>1)&3))
    uint32_t arow = wm * 64 + (lane & 15);
    uint32_t axor = (arow >> 1) & 3;
    uint32_t ahi = lane >> 4;
    uint32_t aoffb = arow * 64;
    uint32_t brow = wn * 32 + (lane & 7) + ((lane & 16) >> 1);
    uint32_t bxor = (brow >> 1) & 3;
    uint32_t bhi = (lane >> 3) & 1;
    uint32_t boffb = brow * 64;

    float acc[4][4][4];
#pragma unroll
    for (int mi = 0; mi < 4; mi++)
#pragma unroll
        for (int ni = 0; ni < 4; ni++)
#pragma unroll
            for (int r = 0; r < 4; r++) acc[mi][ni][r] = 0.f;

#pragma unroll 1
    for (int st = 0; st < NSTS; st++) {
        int buf = st % 3;
        mbar_wait(FULLB + 8 * buf, (uint32_t)((st / 3) & 1));
        uint32_t sbuf = DATA + buf * STAGE_BYTES;
#pragma unroll
        for (int kst = 0; kst < 4; kst++) {
            uint32_t wbo = (uint32_t)(kst >> 1) * 8192;
            uint32_t ac = (((kst & 1) * 2 + ahi) ^ axor) << 4;
            uint32_t bc = (((kst & 1) * 2 + bhi) ^ bxor) << 4;
            uint32_t a[4][4], bfr[2][4];
#pragma unroll
            for (int mi = 0; mi < 4; mi++)
                ldsm4(a[mi], sbuf + wbo + aoffb + mi * 1024 + ac);
#pragma unroll
            for (int np = 0; np < 2; np++)
                ldsm4(bfr[np], sbuf + 16384 + wbo + boffb + np * 1024 + bc);
#pragma unroll
            for (int mi = 0; mi < 4; mi++)
#pragma unroll
                for (int ni = 0; ni < 4; ni++)
                    mma16816(acc[mi][ni], a[mi], &bfr[ni >> 1][(ni & 1) * 2]);
        }
        __syncthreads();
        if (tid == 0) {
            int ip = st + STAGES - 1;
            if (ip < NSTS) {
                int pb = ip % 3;
                uint32_t mb = FULLB + 8 * pb;
                mbar_expect_tx(mb, STAGE_BYTES);
                bulk_g2s(DATA + pb * STAGE_BYTES, wsrc + (size_t)ip * 16384, 16384, mb);
                bulk_g2s(DATA + pb * STAGE_BYTES + 16384, asrc + (size_t)ip * 16384, 16384, mb);
            }
        }
    }

    // epilogue: dense f32 partial tile
    float* pdst = g_P + (size_t)blockIdx.x * 16384;
#pragma unroll
    for (int mi = 0; mi < 4; mi++) {
        int r0 = wm * 64 + mi * 16 + (lane >> 2);
#pragma unroll
        for (int ni = 0; ni < 4; ni++) {
            int c0 = wn * 32 + ni * 8 + 2 * (lane & 3);
#pragma unroll
            for (int r = 0; r < 4; r++) {
                int row = r0 + (r >> 1) * 8;
                int col = c0 + (r & 1);
                pdst[row * 128 + col] = acc[mi][ni][r];
            }
        }
    }
}

// ---------------------------------------------------------------------------
// reduce: sum 3 split partials per tile element, scatter to out[b][l][h][w].
// 196 CTAs x 256 threads; float4 loads, scalar scatter (hw rollover).
// ---------------------------------------------------------------------------
__global__ __launch_bounds__(256) void reduce_kernel(float* __restrict__ out) {
    int tile = blockIdx.x;
    int mt = tile / NTT, nt = tile - mt * NTT;
    const float4* p0 = reinterpret_cast<const float4*>(g_P + (size_t)tile * 16384);
    const float4* p1 = reinterpret_cast<const float4*>(g_P + (size_t)(tile + NTILES) * 16384);
    const float4* p2 = reinterpret_cast<const float4*>(g_P + (size_t)(tile + 2 * NTILES) * 16384);

    int tid = threadIdx.x;
#pragma unroll 4
    for (int it = 0; it < 16; it++) {
        int v = it * 256 + tid;                // float4 index, 4096 per tile
        float4 a = p0[v], b4 = p1[v], c = p2[v];
        float s0 = a.x + b4.x + c.x;
        float s1 = a.y + b4.y + c.y;
        float s2 = a.z + b4.z + c.z;
        float s3 = a.w + b4.w + c.w;
        int idx = v * 4;
        int row = idx >> 7, col = idx & 127;
        int m = mt * 128 + row;
        int n = nt * 128 + col;
        int bb = n / 49, hw = n - bb * 49;
        float* o = out + (size_t)m * 49;
        o[(size_t)bb * 25088 + hw] = s0; if (++hw == 49) { hw = 0; bb++; }
        o[(size_t)bb * 25088 + hw] = s1; if (++hw == 49) { hw = 0; bb++; }
        o[(size_t)bb * 25088 + hw] = s2; if (++hw == 49) { hw = 0; bb++; }
        o[(size_t)bb * 25088 + hw] = s3;
    }
}

// ---------------------------------------------------------------------------
extern "C" void kernel_launch(void* const* d_in, const int* in_sizes, int n_in,
                              void* d_out, int out_size) {
    const float* x  = (const float*)d_in[0];   // [128,512,7,7]
    const float* Wt = (const float*)d_in[1];   // [256,3,3,512]
    float* out = (float*)d_out;                // [128,512,7,7]

    cudaFuncSetAttribute(prep_kernel, cudaFuncAttributeMaxDynamicSharedMemorySize,
                         PREP_SMEM);
    cudaFuncSetAttribute(gemm_kernel, cudaFuncAttributeMaxDynamicSharedMemorySize,
                         GEMM_SMEM);

    prep_kernel<<<272, 256, PREP_SMEM>>>(x, Wt);
    gemm_kernel<<<KSPLIT * NTILES, 256, GEMM_SMEM>>>();
    reduce_kernel<<<NTILES, 256>>>(out);
}